// round 2
// baseline (speedup 1.0000x reference)
#include <cuda_runtime.h>
#include <math.h>

#define DIM    1024
#define SEQ    2048
#define BATCH  2
#define TOK    (BATCH*SEQ)   // 4096
#define HEADS  16
#define HD     64
#define MLPD   4096
#define NLAYER 6
#define SCALE  0.03125f      // DIM^-0.5 (reference uses full dim)
#define EPS    1e-5f

// ---------------- scratch (static device globals; no allocation) ------------
__device__ float g_y[TOK * DIM];              // 16 MB  LN output
__device__ float g_qkv[TOK * 3 * DIM];        // 48 MB  qkv projection
__device__ float g_att[TOK * DIM];            // 16 MB  attention output (b,n,dim)
__device__ float g_mlp[(size_t)TOK * MLPD];   // 64 MB  MLP hidden

// ---------------- simple copy ------------------------------------------------
__global__ __launch_bounds__(256) void copy_kernel(const float* __restrict__ in,
                                                   float* __restrict__ out) {
    size_t i = (size_t)blockIdx.x * 256 + threadIdx.x;
    ((float4*)out)[i] = ((const float4*)in)[i];
}

// ---------------- layernorm: one block per row of 1024 ----------------------
__global__ __launch_bounds__(256) void layernorm_k(const float* __restrict__ x,
                                                   const float* __restrict__ g,
                                                   const float* __restrict__ b,
                                                   float* __restrict__ y) {
    int row = blockIdx.x;
    int t = threadIdx.x;
    float4 v = ((const float4*)(x + (size_t)row * DIM))[t];
    float s = v.x + v.y + v.z + v.w;
    float ss = v.x * v.x + v.y * v.y + v.z * v.z + v.w * v.w;
#pragma unroll
    for (int off = 16; off; off >>= 1) {
        s  += __shfl_xor_sync(0xffffffffu, s, off);
        ss += __shfl_xor_sync(0xffffffffu, ss, off);
    }
    __shared__ float sh[16];
    int w = t >> 5;
    if ((t & 31) == 0) { sh[w] = s; sh[8 + w] = ss; }
    __syncthreads();
    float S = 0.f, SS = 0.f;
#pragma unroll
    for (int i = 0; i < 8; i++) { S += sh[i]; SS += sh[8 + i]; }
    float mean = S * (1.0f / DIM);
    float var  = SS * (1.0f / DIM) - mean * mean;
    float r = rsqrtf(var + EPS);
    float4 gv = ((const float4*)g)[t];
    float4 bv = ((const float4*)b)[t];
    float4 o;
    o.x = (v.x - mean) * r * gv.x + bv.x;
    o.y = (v.y - mean) * r * gv.y + bv.y;
    o.z = (v.z - mean) * r * gv.z + bv.z;
    o.w = (v.w - mean) * r * gv.w + bv.w;
    ((float4*)(y + (size_t)row * DIM))[t] = o;
}

// ---------------- SGEMM: C[M,N] = A[M,K] @ B[K,N], tiled 128x128x16 ---------
// EPI 0: C = AB
// EPI 1: C = gelu(AB + bias)        (exact erf gelu)
// EPI 2: C = C + AB + bias          (residual accumulate)
#define BM 128
#define BN 128
#define BK 16

__device__ __forceinline__ float gelu_exact(float x) {
    return 0.5f * x * (1.0f + erff(x * 0.70710678118654752f));
}

template <int EPI>
__global__ __launch_bounds__(256) void sgemm_k(const float* __restrict__ A,
                                               const float* __restrict__ B,
                                               const float* __restrict__ bias,
                                               float* __restrict__ C,
                                               int M, int N, int K) {
    __shared__ float As[BK][BM];   // transposed A tile
    __shared__ float Bs[BK][BN];
    int t = threadIdx.x;
    int bm = blockIdx.y * BM;
    int bn = blockIdx.x * BN;

    int aRow = t >> 2;            // 0..63
    int aCol = (t & 3) << 2;      // 0,4,8,12
    int bRow = t >> 5;            // 0..7
    int bCol = (t & 31) << 2;     // 0..124

    int ty = t >> 4;              // 0..15
    int tx = t & 15;              // 0..15

    float acc[8][8];
#pragma unroll
    for (int i = 0; i < 8; i++)
#pragma unroll
        for (int j = 0; j < 8; j++) acc[i][j] = 0.f;

    for (int k0 = 0; k0 < K; k0 += BK) {
#pragma unroll
        for (int i = 0; i < 2; i++) {
            int r = aRow + i * 64;
            float4 v = *(const float4*)(A + (size_t)(bm + r) * K + k0 + aCol);
            As[aCol + 0][r] = v.x;
            As[aCol + 1][r] = v.y;
            As[aCol + 2][r] = v.z;
            As[aCol + 3][r] = v.w;
        }
#pragma unroll
        for (int i = 0; i < 2; i++) {
            int r = bRow + i * 8;
            *(float4*)(&Bs[r][bCol]) =
                *(const float4*)(B + (size_t)(k0 + r) * N + bn + bCol);
        }
        __syncthreads();
#pragma unroll
        for (int k = 0; k < BK; k++) {
            float a[8], b[8];
#pragma unroll
            for (int i = 0; i < 8; i++) a[i] = As[k][ty * 8 + i];
#pragma unroll
            for (int j = 0; j < 8; j++) b[j] = Bs[k][tx * 8 + j];
#pragma unroll
            for (int i = 0; i < 8; i++)
#pragma unroll
                for (int j = 0; j < 8; j++) acc[i][j] += a[i] * b[j];
        }
        __syncthreads();
    }

    // epilogue
#pragma unroll
    for (int i = 0; i < 8; i++) {
        size_t row = bm + ty * 8 + i;
        float* cp = C + row * N + bn + tx * 8;
#pragma unroll
        for (int jj = 0; jj < 8; jj += 4) {
            float4 r;
            if (EPI == 0) {
                r = make_float4(acc[i][jj], acc[i][jj + 1], acc[i][jj + 2], acc[i][jj + 3]);
            } else if (EPI == 1) {
                const float* bp = bias + bn + tx * 8 + jj;
                r.x = gelu_exact(acc[i][jj + 0] + bp[0]);
                r.y = gelu_exact(acc[i][jj + 1] + bp[1]);
                r.z = gelu_exact(acc[i][jj + 2] + bp[2]);
                r.w = gelu_exact(acc[i][jj + 3] + bp[3]);
            } else {
                const float* bp = bias + bn + tx * 8 + jj;
                float4 old = *(const float4*)(cp + jj);
                r.x = old.x + acc[i][jj + 0] + bp[0];
                r.y = old.y + acc[i][jj + 1] + bp[1];
                r.z = old.z + acc[i][jj + 2] + bp[2];
                r.w = old.w + acc[i][jj + 3] + bp[3];
            }
            *(float4*)(cp + jj) = r;
        }
    }
}

// ---------------- flash attention: 64-query x 64-key tiles, d=64 ------------
// qkv layout: row = b*SEQ + n (stride 3*DIM); q at col h*64, k at 1024+h*64,
// v at 2048+h*64. Output written as [b*SEQ+n, h*64+d] into [TOK, DIM].
#define APAD 68   // row stride in floats (272B: 16B-aligned, low conflicts)

__global__ __launch_bounds__(256) void attention_k(const float* __restrict__ qkv,
                                                   float* __restrict__ out) {
    extern __shared__ float sm[];
    float* Qt = sm;                 // [d][q]   : Qt[d*APAD + q]
    float* Kt = sm + APAD * 64;     // [d][key] : Kt[d*APAD + key]
    float* Vs = sm + 2 * APAD * 64; // [key][d] : Vs[key*APAD + d]
    float* Ps = sm + 3 * APAD * 64; // [q][key] : Ps[q*APAD + key]

    int q0 = blockIdx.x * 64;
    int h  = blockIdx.y;
    int bb = blockIdx.z;
    int t = threadIdx.x;
    int ty = t >> 4, tx = t & 15;

    const size_t rowstride = 3 * DIM;
    const float* qbase = qkv + (size_t)(bb * SEQ) * rowstride + h * HD;

    // load + transpose Q tile once
    for (int i = t; i < 64 * 16; i += 256) {
        int r = i >> 4;
        int c4 = (i & 15) << 2;
        float4 v = *(const float4*)(qbase + (size_t)(q0 + r) * rowstride + c4);
        Qt[(c4 + 0) * APAD + r] = v.x;
        Qt[(c4 + 1) * APAD + r] = v.y;
        Qt[(c4 + 2) * APAD + r] = v.z;
        Qt[(c4 + 3) * APAD + r] = v.w;
    }

    float m[4], l[4], o[4][4];
#pragma unroll
    for (int i = 0; i < 4; i++) {
        m[i] = -1e30f;
        l[i] = 0.f;
#pragma unroll
        for (int j = 0; j < 4; j++) o[i][j] = 0.f;
    }

    for (int kt = 0; kt < SEQ; kt += 64) {
        __syncthreads();  // protect Kt/Vs/Ps from previous iteration readers
        // load K (transposed) and V tiles
        for (int i = t; i < 64 * 16; i += 256) {
            int r = i >> 4;
            int c4 = (i & 15) << 2;
            const float* kb = qbase + DIM + (size_t)(kt + r) * rowstride + c4;
            float4 kv = *(const float4*)kb;
            Kt[(c4 + 0) * APAD + r] = kv.x;
            Kt[(c4 + 1) * APAD + r] = kv.y;
            Kt[(c4 + 2) * APAD + r] = kv.z;
            Kt[(c4 + 3) * APAD + r] = kv.w;
            const float* vb = qbase + 2 * DIM + (size_t)(kt + r) * rowstride + c4;
            *(float4*)(&Vs[r * APAD + c4]) = *(const float4*)vb;
        }
        __syncthreads();

        // S = Q @ K^T (contraction over d)
        float s[4][4];
#pragma unroll
        for (int i = 0; i < 4; i++)
#pragma unroll
            for (int j = 0; j < 4; j++) s[i][j] = 0.f;
#pragma unroll 8
        for (int kk = 0; kk < 64; kk++) {
            float a[4], b[4];
#pragma unroll
            for (int i = 0; i < 4; i++) a[i] = Qt[kk * APAD + ty * 4 + i];
#pragma unroll
            for (int j = 0; j < 4; j++) b[j] = Kt[kk * APAD + tx * 4 + j];
#pragma unroll
            for (int i = 0; i < 4; i++)
#pragma unroll
                for (int j = 0; j < 4; j++) s[i][j] += a[i] * b[j];
        }

        // online softmax (row groups span 16 contiguous lanes: reduce via xor)
#pragma unroll
        for (int i = 0; i < 4; i++) {
            float mx = -1e30f;
#pragma unroll
            for (int j = 0; j < 4; j++) {
                s[i][j] *= SCALE;
                mx = fmaxf(mx, s[i][j]);
            }
#pragma unroll
            for (int off = 8; off; off >>= 1)
                mx = fmaxf(mx, __shfl_xor_sync(0xffffffffu, mx, off));
            float nm = fmaxf(m[i], mx);
            float alpha = __expf(m[i] - nm);
            float ps = 0.f;
#pragma unroll
            for (int j = 0; j < 4; j++) {
                s[i][j] = __expf(s[i][j] - nm);
                ps += s[i][j];
            }
#pragma unroll
            for (int off = 8; off; off >>= 1)
                ps += __shfl_xor_sync(0xffffffffu, ps, off);
            l[i] = l[i] * alpha + ps;
            m[i] = nm;
#pragma unroll
            for (int j = 0; j < 4; j++) o[i][j] *= alpha;
        }

        // write P to shared (float4, aligned)
#pragma unroll
        for (int i = 0; i < 4; i++)
            *(float4*)(&Ps[(ty * 4 + i) * APAD + tx * 4]) =
                make_float4(s[i][0], s[i][1], s[i][2], s[i][3]);
        __syncthreads();

        // O += P @ V (contraction over key)
#pragma unroll 8
        for (int kk = 0; kk < 64; kk++) {
            float a[4], b[4];
#pragma unroll
            for (int i = 0; i < 4; i++) a[i] = Ps[(ty * 4 + i) * APAD + kk];
#pragma unroll
            for (int j = 0; j < 4; j++) b[j] = Vs[kk * APAD + tx * 4 + j];
#pragma unroll
            for (int i = 0; i < 4; i++)
#pragma unroll
                for (int j = 0; j < 4; j++) o[i][j] += a[i] * b[j];
        }
    }

    // finalize
#pragma unroll
    for (int i = 0; i < 4; i++) {
        float inv = 1.0f / l[i];
        float4 r = make_float4(o[i][0] * inv, o[i][1] * inv,
                               o[i][2] * inv, o[i][3] * inv);
        *(float4*)(out + (size_t)(bb * SEQ + q0 + ty * 4 + i) * DIM +
                   h * HD + tx * 4) = r;
    }
}

#define ATT_SMEM (4 * APAD * 64 * sizeof(float))  // 69632 B

// ---------------- driver -----------------------------------------------------
extern "C" void kernel_launch(void* const* d_in, const int* in_sizes, int n_in,
                              void* d_out, int out_size) {
    const float* x    = (const float*)d_in[0];
    const float* Wqkv = (const float*)d_in[1];
    const float* Wout = (const float*)d_in[2];
    const float* bout = (const float*)d_in[3];
    const float* ln1g = (const float*)d_in[4];
    const float* ln1b = (const float*)d_in[5];
    const float* ln2g = (const float*)d_in[6];
    const float* ln2b = (const float*)d_in[7];
    const float* W1   = (const float*)d_in[8];
    const float* b1   = (const float*)d_in[9];
    const float* W2   = (const float*)d_in[10];
    const float* b2   = (const float*)d_in[11];

    float* h = (float*)d_out;  // residual stream lives in d_out

    float *py, *pqkv, *patt, *pmlp;
    cudaGetSymbolAddress((void**)&py,   g_y);
    cudaGetSymbolAddress((void**)&pqkv, g_qkv);
    cudaGetSymbolAddress((void**)&patt, g_att);
    cudaGetSymbolAddress((void**)&pmlp, g_mlp);

    cudaFuncSetAttribute(attention_k, cudaFuncAttributeMaxDynamicSharedMemorySize,
                         (int)ATT_SMEM);

    // h = x
    copy_kernel<<<TOK * DIM / (256 * 4), 256>>>(x, h);

    for (int l = 0; l < NLAYER; l++) {
        const float* wqkv = Wqkv + (size_t)l * DIM * 3 * DIM;
        const float* wout = Wout + (size_t)l * DIM * DIM;
        const float* bo   = bout + (size_t)l * DIM;
        const float* g1   = ln1g + (size_t)l * DIM;
        const float* bb1  = ln1b + (size_t)l * DIM;
        const float* g2   = ln2g + (size_t)l * DIM;
        const float* bb2  = ln2b + (size_t)l * DIM;
        const float* w1   = W1 + (size_t)l * DIM * MLPD;
        const float* bf1  = b1 + (size_t)l * MLPD;
        const float* w2   = W2 + (size_t)l * MLPD * DIM;
        const float* bf2  = b2 + (size_t)l * DIM;

        // --- attention block ---
        layernorm_k<<<TOK, 256>>>(h, g1, bb1, py);
        sgemm_k<0><<<dim3(3 * DIM / BN, TOK / BM), 256>>>(py, wqkv, nullptr, pqkv,
                                                          TOK, 3 * DIM, DIM);
        attention_k<<<dim3(SEQ / 64, HEADS, BATCH), 256, ATT_SMEM>>>(pqkv, patt);
        sgemm_k<2><<<dim3(DIM / BN, TOK / BM), 256>>>(patt, wout, bo, h,
                                                      TOK, DIM, DIM);

        // --- FFN block ---
        layernorm_k<<<TOK, 256>>>(h, g2, bb2, py);
        sgemm_k<1><<<dim3(MLPD / BN, TOK / BM), 256>>>(py, w1, bf1, pmlp,
                                                       TOK, MLPD, DIM);
        sgemm_k<2><<<dim3(DIM / BN, TOK / BM), 256>>>(pmlp, w2, bf2, h,
                                                      TOK, DIM, MLPD);
    }
}

// round 4
// speedup vs baseline: 1.5922x; 1.5922x over previous
#include <cuda_runtime.h>
#include <cuda_bf16.h>
#include <math.h>
#include <stdint.h>

#define DIM    1024
#define SEQ    2048
#define BATCH  2
#define TOK    (BATCH*SEQ)   // 4096
#define HEADS  16
#define HD     64
#define MLPD   4096
#define NLAYER 6
#define SCALE  0.03125f
#define EPS    1e-5f

typedef __nv_bfloat16 bf16;

// ---------------- scratch (static device globals; no allocation) ------------
__device__ float g_qkv[TOK * 3 * DIM];                      // fp32 for attention
__device__ bf16  g_yh[TOK * DIM],  g_yl[TOK * DIM];         // LN out hi/lo
__device__ bf16  g_ah[TOK * DIM],  g_al[TOK * DIM];         // attention out hi/lo
__device__ bf16  g_mh[(size_t)TOK * MLPD], g_ml[(size_t)TOK * MLPD]; // MLP hidden
// transposed+split weights [N,K] bf16, per layer, hi then lo
__device__ bf16  g_wqkvT[2][NLAYER][3 * DIM * DIM];
__device__ bf16  g_woutT[2][NLAYER][DIM * DIM];
__device__ bf16  g_w1T[2][NLAYER][(size_t)DIM * MLPD];
__device__ bf16  g_w2T[2][NLAYER][(size_t)DIM * MLPD];

// ---------------- PTX helpers (sm_80-class only: valid on plain sm_103) -----
__device__ __forceinline__ uint32_t smem_u32(const void* p) {
    uint32_t a;
    asm("{ .reg .u64 t; cvta.to.shared.u64 t, %1; cvt.u32.u64 %0, t; }"
        : "=r"(a) : "l"(p));
    return a;
}
#define LDSM4(r, addr) \
    asm volatile("ldmatrix.sync.aligned.m8n8.x4.shared.b16 {%0,%1,%2,%3}, [%4];" \
        : "=r"((r)[0]), "=r"((r)[1]), "=r"((r)[2]), "=r"((r)[3]) : "r"(addr))
#define LDSM2(r, addr) \
    asm volatile("ldmatrix.sync.aligned.m8n8.x2.shared.b16 {%0,%1}, [%2];" \
        : "=r"((r)[0]), "=r"((r)[1]) : "r"(addr))
#define MMA16816(d, a, b) \
    asm volatile("mma.sync.aligned.m16n8k16.row.col.f32.bf16.bf16.f32 " \
        "{%0,%1,%2,%3}, {%4,%5,%6,%7}, {%8,%9}, {%0,%1,%2,%3};" \
        : "+f"((d)[0]), "+f"((d)[1]), "+f"((d)[2]), "+f"((d)[3]) \
        : "r"((a)[0]), "r"((a)[1]), "r"((a)[2]), "r"((a)[3]), \
          "r"((b)[0]), "r"((b)[1]))
#define CP_ASYNC16(dst, src) \
    asm volatile("cp.async.cg.shared.global [%0], [%1], 16;" \
        :: "r"(dst), "l"(src) : "memory")
#define CP_COMMIT() asm volatile("cp.async.commit_group;" ::: "memory")
#define CP_WAIT(n)  asm volatile("cp.async.wait_group %0;" :: "n"(n) : "memory")

__device__ __forceinline__ void split2(float a, float b, uint32_t& hi, uint32_t& lo) {
    __nv_bfloat16 ah = __float2bfloat16(a), bh = __float2bfloat16(b);
    __nv_bfloat162 H, L;
    H.x = ah; H.y = bh;
    L.x = __float2bfloat16(a - __bfloat162float(ah));
    L.y = __float2bfloat16(b - __bfloat162float(bh));
    hi = *(uint32_t*)&H; lo = *(uint32_t*)&L;
}
__device__ __forceinline__ float gelu_exact(float x) {
    return 0.5f * x * (1.0f + erff(x * 0.70710678118654752f));
}

// ---------------- simple copy ------------------------------------------------
__global__ __launch_bounds__(256) void copy_kernel(const float* __restrict__ in,
                                                   float* __restrict__ out) {
    size_t i = (size_t)blockIdx.x * 256 + threadIdx.x;
    ((float4*)out)[i] = ((const float4*)in)[i];
}

// ---------------- weight transpose + bf16 split: W[K,N] -> T{hi,lo}[N,K] ----
__global__ __launch_bounds__(256) void transpose_split_k(const float* __restrict__ W,
                                                         bf16* __restrict__ Thi,
                                                         bf16* __restrict__ Tlo,
                                                         int K, int N) {
    __shared__ float s[32][33];
    int n0 = blockIdx.x * 32, k0 = blockIdx.y * 32;
    int tx = threadIdx.x & 31, ty = threadIdx.x >> 5;   // ty 0..7
#pragma unroll
    for (int i = 0; i < 4; i++)
        s[ty + 8 * i][tx] = W[(size_t)(k0 + ty + 8 * i) * N + n0 + tx];
    __syncthreads();
#pragma unroll
    for (int i = 0; i < 4; i++) {
        float v = s[tx][ty + 8 * i];
        int n = n0 + ty + 8 * i, k = k0 + tx;
        bf16 hi = __float2bfloat16(v);
        Thi[(size_t)n * K + k] = hi;
        Tlo[(size_t)n * K + k] = __float2bfloat16(v - __bfloat162float(hi));
    }
}

// ---------------- layernorm -> split bf16 hi/lo ------------------------------
__global__ __launch_bounds__(256) void layernorm_k(const float* __restrict__ x,
                                                   const float* __restrict__ g,
                                                   const float* __restrict__ b,
                                                   bf16* __restrict__ yh,
                                                   bf16* __restrict__ yl) {
    int row = blockIdx.x;
    int t = threadIdx.x;
    float4 v = ((const float4*)(x + (size_t)row * DIM))[t];
    float s = v.x + v.y + v.z + v.w;
    float ss = v.x * v.x + v.y * v.y + v.z * v.z + v.w * v.w;
#pragma unroll
    for (int off = 16; off; off >>= 1) {
        s  += __shfl_xor_sync(0xffffffffu, s, off);
        ss += __shfl_xor_sync(0xffffffffu, ss, off);
    }
    __shared__ float sh[16];
    int w = t >> 5;
    if ((t & 31) == 0) { sh[w] = s; sh[8 + w] = ss; }
    __syncthreads();
    float S = 0.f, SS = 0.f;
#pragma unroll
    for (int i = 0; i < 8; i++) { S += sh[i]; SS += sh[8 + i]; }
    float mean = S * (1.0f / DIM);
    float var  = SS * (1.0f / DIM) - mean * mean;
    float r = rsqrtf(var + EPS);
    float4 gv = ((const float4*)g)[t];
    float4 bv = ((const float4*)b)[t];
    float o0 = (v.x - mean) * r * gv.x + bv.x;
    float o1 = (v.y - mean) * r * gv.y + bv.y;
    float o2 = (v.z - mean) * r * gv.z + bv.z;
    float o3 = (v.w - mean) * r * gv.w + bv.w;
    uint32_t h0, l0, h1, l1;
    split2(o0, o1, h0, l0); split2(o2, o3, h1, l1);
    *(uint2*)(yh + (size_t)row * DIM + t * 4) = make_uint2(h0, h1);
    *(uint2*)(yl + (size_t)row * DIM + t * 4) = make_uint2(l0, l1);
}

// ---------------- warp-MMA split-bf16 GEMM -----------------------------------
// C[M,N] = A[M,K] @ B^T with B stored [N,K]; A,B as (hi,lo) bf16 pairs.
// CTA tile 128x128, 8 warps (2 in m x 4 in n), warp tile 64x32, mma m16n8k16.
// EPI 0: C fp32 = AB
// EPI 1: gelu(AB + bias) -> Ohi/Olo bf16 split
// EPI 2: C fp32 += AB + bias
#define GBK    32                  // K-chunk
#define GSTR   40                  // smem row stride in bf16 (80 B, conflict-free)
#define GTILE  (128 * GSTR * 2)    // 10240 B per tile
#define GSTAGE (4 * GTILE)         // Ahi|Alo|Bhi|Blo = 40960 B
#define GEMM_SMEM (2 * GSTAGE)     // 81920 B

template <int EPI>
__global__ __launch_bounds__(256, 1) void gemm_mma_k(
    const bf16* __restrict__ Ahi, const bf16* __restrict__ Alo,
    const bf16* __restrict__ Bhi, const bf16* __restrict__ Blo,
    const float* __restrict__ bias, float* __restrict__ C,
    bf16* __restrict__ Ohi, bf16* __restrict__ Olo,
    int N, int K) {
    extern __shared__ __align__(1024) char smem[];
    uint32_t sb = smem_u32(smem);
    int tid = threadIdx.x;
    int lane = tid & 31, wid = tid >> 5;
    int wm = wid & 1, wn = wid >> 1;          // warp grid 2 x 4
    int bm = blockIdx.y * 128, bn = blockIdx.x * 128;

    // ldmatrix per-lane base offsets (bytes within a tile)
    int matA = lane >> 3;                      // 0..3
    int rowA = wm * 64 + (matA & 1) * 8 + (lane & 7);
    int colA = (matA >> 1) * 8;
    uint32_t offA0 = (uint32_t)((rowA * GSTR + colA) * 2);
    int lb = lane & 15;                        // lanes 16-31 replicate (ignored)
    int rowB = wn * 32 + (lb & 7);
    int colB = (lb >> 3) * 8;
    uint32_t offB0 = (uint32_t)((rowB * GSTR + colB) * 2) + 2 * (uint32_t)GTILE;

    float acc[4][4][4];
#pragma unroll
    for (int i = 0; i < 4; i++)
#pragma unroll
        for (int j = 0; j < 4; j++)
#pragma unroll
            for (int r = 0; r < 4; r++) acc[i][j][r] = 0.f;

    // async load of one chunk into stage s
    auto issue = [&](int s, int kc) {
        uint32_t stoff = sb + s * GSTAGE;
#pragma unroll
        for (int it = 0; it < 8; ++it) {
            int idx = it * 256 + tid;
            int tl = it >> 1;                 // tile id, uniform per it
            int j = idx & 511;
            int r = j >> 2;
            int c = j & 3;                    // 16B column
            const bf16* src = (tl == 0) ? Ahi : (tl == 1) ? Alo
                            : (tl == 2) ? Bhi : Blo;
            int row0 = (tl < 2) ? bm : bn;
            const bf16* gp = src + (size_t)(row0 + r) * K + kc + c * 8;
            uint32_t dp = stoff + tl * GTILE + (uint32_t)((r * GSTR + c * 8) * 2);
            CP_ASYNC16(dp, gp);
        }
    };

    issue(0, 0);
    CP_COMMIT();

    const int NC = K / GBK;
    for (int c = 0; c < NC; ++c) {
        if (c + 1 < NC) {
            issue((c + 1) & 1, (c + 1) * GBK);
            CP_COMMIT();
            CP_WAIT(1);
        } else {
            CP_WAIT(0);
        }
        __syncthreads();

        uint32_t st = sb + (c & 1) * GSTAGE;
#pragma unroll
        for (int kk = 0; kk < 2; ++kk) {
            uint32_t kb = st + kk * 32;       // 16 bf16 = 32 B k-offset
            uint32_t a[4][2][4], b[4][2][2];
#pragma unroll
            for (int i = 0; i < 4; i++) {
                LDSM4(a[i][0], kb + offA0 + i * (16 * GSTR * 2));
                LDSM4(a[i][1], kb + offA0 + i * (16 * GSTR * 2) + GTILE);
            }
#pragma unroll
            for (int j = 0; j < 4; j++) {
                LDSM2(b[j][0], kb + offB0 + j * (8 * GSTR * 2));
                LDSM2(b[j][1], kb + offB0 + j * (8 * GSTR * 2) + GTILE);
            }
#pragma unroll
            for (int i = 0; i < 4; i++)
#pragma unroll
                for (int j = 0; j < 4; j++) {
                    MMA16816(acc[i][j], a[i][0], b[j][0]);
                    MMA16816(acc[i][j], a[i][0], b[j][1]);
                    MMA16816(acc[i][j], a[i][1], b[j][0]);
                }
        }
        __syncthreads();
    }

    // epilogue straight from registers
    int g = lane >> 2, tg = (lane & 3) * 2;
#pragma unroll
    for (int i = 0; i < 4; i++) {
        int row = bm + wm * 64 + i * 16 + g;
#pragma unroll
        for (int j = 0; j < 4; j++) {
            int col = bn + wn * 32 + j * 8 + tg;
#pragma unroll
            for (int half = 0; half < 2; half++) {
                int rr = row + half * 8;
                float v0 = acc[i][j][half * 2 + 0];
                float v1 = acc[i][j][half * 2 + 1];
                if (EPI == 0) {
                    *(float2*)(C + (size_t)rr * N + col) = make_float2(v0, v1);
                } else if (EPI == 1) {
                    float a0 = gelu_exact(v0 + __ldg(bias + col));
                    float a1 = gelu_exact(v1 + __ldg(bias + col + 1));
                    uint32_t hi, lo;
                    split2(a0, a1, hi, lo);
                    *(uint32_t*)(Ohi + (size_t)rr * N + col) = hi;
                    *(uint32_t*)(Olo + (size_t)rr * N + col) = lo;
                } else {
                    float2 old = *(float2*)(C + (size_t)rr * N + col);
                    old.x += v0 + __ldg(bias + col);
                    old.y += v1 + __ldg(bias + col + 1);
                    *(float2*)(C + (size_t)rr * N + col) = old;
                }
            }
        }
    }
}

// ---------------- flash attention (fp32 FFMA), output split to bf16 ----------
#define APAD 68

__global__ __launch_bounds__(256) void attention_k(const float* __restrict__ qkv,
                                                   bf16* __restrict__ oh,
                                                   bf16* __restrict__ ol) {
    extern __shared__ float sm[];
    float* Qt = sm;
    float* Kt = sm + APAD * 64;
    float* Vs = sm + 2 * APAD * 64;
    float* Ps = sm + 3 * APAD * 64;

    int q0 = blockIdx.x * 64;
    int h  = blockIdx.y;
    int bb = blockIdx.z;
    int t = threadIdx.x;
    int ty = t >> 4, tx = t & 15;

    const size_t rowstride = 3 * DIM;
    const float* qbase = qkv + (size_t)(bb * SEQ) * rowstride + h * HD;

    for (int i = t; i < 64 * 16; i += 256) {
        int r = i >> 4;
        int c4 = (i & 15) << 2;
        float4 v = *(const float4*)(qbase + (size_t)(q0 + r) * rowstride + c4);
        Qt[(c4 + 0) * APAD + r] = v.x;
        Qt[(c4 + 1) * APAD + r] = v.y;
        Qt[(c4 + 2) * APAD + r] = v.z;
        Qt[(c4 + 3) * APAD + r] = v.w;
    }

    float m[4], l[4], o[4][4];
#pragma unroll
    for (int i = 0; i < 4; i++) {
        m[i] = -1e30f; l[i] = 0.f;
#pragma unroll
        for (int j = 0; j < 4; j++) o[i][j] = 0.f;
    }

    for (int kt = 0; kt < SEQ; kt += 64) {
        __syncthreads();
        for (int i = t; i < 64 * 16; i += 256) {
            int r = i >> 4;
            int c4 = (i & 15) << 2;
            const float* kb = qbase + DIM + (size_t)(kt + r) * rowstride + c4;
            float4 kv = *(const float4*)kb;
            Kt[(c4 + 0) * APAD + r] = kv.x;
            Kt[(c4 + 1) * APAD + r] = kv.y;
            Kt[(c4 + 2) * APAD + r] = kv.z;
            Kt[(c4 + 3) * APAD + r] = kv.w;
            const float* vb = qbase + 2 * DIM + (size_t)(kt + r) * rowstride + c4;
            *(float4*)(&Vs[r * APAD + c4]) = *(const float4*)vb;
        }
        __syncthreads();

        float s[4][4];
#pragma unroll
        for (int i = 0; i < 4; i++)
#pragma unroll
            for (int j = 0; j < 4; j++) s[i][j] = 0.f;
#pragma unroll 8
        for (int kk = 0; kk < 64; kk++) {
            float a[4], b[4];
#pragma unroll
            for (int i = 0; i < 4; i++) a[i] = Qt[kk * APAD + ty * 4 + i];
#pragma unroll
            for (int j = 0; j < 4; j++) b[j] = Kt[kk * APAD + tx * 4 + j];
#pragma unroll
            for (int i = 0; i < 4; i++)
#pragma unroll
                for (int j = 0; j < 4; j++) s[i][j] += a[i] * b[j];
        }

#pragma unroll
        for (int i = 0; i < 4; i++) {
            float mx = -1e30f;
#pragma unroll
            for (int j = 0; j < 4; j++) { s[i][j] *= SCALE; mx = fmaxf(mx, s[i][j]); }
#pragma unroll
            for (int off = 8; off; off >>= 1)
                mx = fmaxf(mx, __shfl_xor_sync(0xffffffffu, mx, off));
            float nm = fmaxf(m[i], mx);
            float alpha = __expf(m[i] - nm);
            float ps = 0.f;
#pragma unroll
            for (int j = 0; j < 4; j++) { s[i][j] = __expf(s[i][j] - nm); ps += s[i][j]; }
#pragma unroll
            for (int off = 8; off; off >>= 1)
                ps += __shfl_xor_sync(0xffffffffu, ps, off);
            l[i] = l[i] * alpha + ps;
            m[i] = nm;
#pragma unroll
            for (int j = 0; j < 4; j++) o[i][j] *= alpha;
        }

#pragma unroll
        for (int i = 0; i < 4; i++)
            *(float4*)(&Ps[(ty * 4 + i) * APAD + tx * 4]) =
                make_float4(s[i][0], s[i][1], s[i][2], s[i][3]);
        __syncthreads();

#pragma unroll 8
        for (int kk = 0; kk < 64; kk++) {
            float a[4], b[4];
#pragma unroll
            for (int i = 0; i < 4; i++) a[i] = Ps[(ty * 4 + i) * APAD + kk];
#pragma unroll
            for (int j = 0; j < 4; j++) b[j] = Vs[kk * APAD + tx * 4 + j];
#pragma unroll
            for (int i = 0; i < 4; i++)
#pragma unroll
                for (int j = 0; j < 4; j++) o[i][j] += a[i] * b[j];
        }
    }

#pragma unroll
    for (int i = 0; i < 4; i++) {
        float inv = 1.0f / l[i];
        float v0 = o[i][0] * inv, v1 = o[i][1] * inv;
        float v2 = o[i][2] * inv, v3 = o[i][3] * inv;
        uint32_t h0, l0, h1, l1;
        split2(v0, v1, h0, l0); split2(v2, v3, h1, l1);
        size_t idx = (size_t)(bb * SEQ + q0 + ty * 4 + i) * DIM + h * HD + tx * 4;
        *(uint2*)(oh + idx) = make_uint2(h0, h1);
        *(uint2*)(ol + idx) = make_uint2(l0, l1);
    }
}
#define ATT_SMEM (4 * APAD * 64 * sizeof(float))

// ---------------- driver -----------------------------------------------------
extern "C" void kernel_launch(void* const* d_in, const int* in_sizes, int n_in,
                              void* d_out, int out_size) {
    const float* x    = (const float*)d_in[0];
    const float* Wqkv = (const float*)d_in[1];
    const float* Wout = (const float*)d_in[2];
    const float* bout = (const float*)d_in[3];
    const float* ln1g = (const float*)d_in[4];
    const float* ln1b = (const float*)d_in[5];
    const float* ln2g = (const float*)d_in[6];
    const float* ln2b = (const float*)d_in[7];
    const float* W1   = (const float*)d_in[8];
    const float* b1   = (const float*)d_in[9];
    const float* W2   = (const float*)d_in[10];
    const float* b2   = (const float*)d_in[11];

    float* h = (float*)d_out;

    float* pqkv;
    bf16 *pyh, *pyl, *pah, *pal, *pmh, *pml;
    bf16 *pwqkvT, *pwoutT, *pw1T, *pw2T;
    cudaGetSymbolAddress((void**)&pqkv,   g_qkv);
    cudaGetSymbolAddress((void**)&pyh,    g_yh);
    cudaGetSymbolAddress((void**)&pyl,    g_yl);
    cudaGetSymbolAddress((void**)&pah,    g_ah);
    cudaGetSymbolAddress((void**)&pal,    g_al);
    cudaGetSymbolAddress((void**)&pmh,    g_mh);
    cudaGetSymbolAddress((void**)&pml,    g_ml);
    cudaGetSymbolAddress((void**)&pwqkvT, g_wqkvT);
    cudaGetSymbolAddress((void**)&pwoutT, g_woutT);
    cudaGetSymbolAddress((void**)&pw1T,   g_w1T);
    cudaGetSymbolAddress((void**)&pw2T,   g_w2T);

    cudaFuncSetAttribute(attention_k, cudaFuncAttributeMaxDynamicSharedMemorySize, (int)ATT_SMEM);
    cudaFuncSetAttribute(gemm_mma_k<0>, cudaFuncAttributeMaxDynamicSharedMemorySize, GEMM_SMEM);
    cudaFuncSetAttribute(gemm_mma_k<1>, cudaFuncAttributeMaxDynamicSharedMemorySize, GEMM_SMEM);
    cudaFuncSetAttribute(gemm_mma_k<2>, cudaFuncAttributeMaxDynamicSharedMemorySize, GEMM_SMEM);

    const size_t SZ_QKV = (size_t)3 * DIM * DIM;
    const size_t SZ_OUT = (size_t)DIM * DIM;
    const size_t SZ_MLP = (size_t)DIM * MLPD;

    // one-time (per launch) weight transpose + split
    for (int l = 0; l < NLAYER; l++) {
        transpose_split_k<<<dim3(3 * DIM / 32, DIM / 32), 256>>>(
            Wqkv + (size_t)l * SZ_QKV,
            pwqkvT + (size_t)l * SZ_QKV, pwqkvT + ((size_t)NLAYER + l) * SZ_QKV,
            DIM, 3 * DIM);
        transpose_split_k<<<dim3(DIM / 32, DIM / 32), 256>>>(
            Wout + (size_t)l * SZ_OUT,
            pwoutT + (size_t)l * SZ_OUT, pwoutT + ((size_t)NLAYER + l) * SZ_OUT,
            DIM, DIM);
        transpose_split_k<<<dim3(MLPD / 32, DIM / 32), 256>>>(
            W1 + (size_t)l * SZ_MLP,
            pw1T + (size_t)l * SZ_MLP, pw1T + ((size_t)NLAYER + l) * SZ_MLP,
            DIM, MLPD);
        transpose_split_k<<<dim3(DIM / 32, MLPD / 32), 256>>>(
            W2 + (size_t)l * SZ_MLP,
            pw2T + (size_t)l * SZ_MLP, pw2T + ((size_t)NLAYER + l) * SZ_MLP,
            MLPD, DIM);
    }

    copy_kernel<<<TOK * DIM / (256 * 4), 256>>>(x, h);

    for (int l = 0; l < NLAYER; l++) {
        const float* bo  = bout + (size_t)l * DIM;
        const float* g1  = ln1g + (size_t)l * DIM;
        const float* bb1 = ln1b + (size_t)l * DIM;
        const float* g2  = ln2g + (size_t)l * DIM;
        const float* bb2 = ln2b + (size_t)l * DIM;
        const float* bf1 = b1 + (size_t)l * MLPD;
        const float* bf2 = b2 + (size_t)l * DIM;

        bf16* qkvT_h = pwqkvT + (size_t)l * SZ_QKV;
        bf16* qkvT_l = pwqkvT + ((size_t)NLAYER + l) * SZ_QKV;
        bf16* outT_h = pwoutT + (size_t)l * SZ_OUT;
        bf16* outT_l = pwoutT + ((size_t)NLAYER + l) * SZ_OUT;
        bf16* w1T_h  = pw1T + (size_t)l * SZ_MLP;
        bf16* w1T_l  = pw1T + ((size_t)NLAYER + l) * SZ_MLP;
        bf16* w2T_h  = pw2T + (size_t)l * SZ_MLP;
        bf16* w2T_l  = pw2T + ((size_t)NLAYER + l) * SZ_MLP;

        // --- attention block ---
        layernorm_k<<<TOK, 256>>>(h, g1, bb1, pyh, pyl);
        gemm_mma_k<0><<<dim3(3 * DIM / 128, TOK / 128), 256, GEMM_SMEM>>>(
            pyh, pyl, qkvT_h, qkvT_l, nullptr, pqkv, nullptr, nullptr, 3 * DIM, DIM);
        attention_k<<<dim3(SEQ / 64, HEADS, BATCH), 256, ATT_SMEM>>>(pqkv, pah, pal);
        gemm_mma_k<2><<<dim3(DIM / 128, TOK / 128), 256, GEMM_SMEM>>>(
            pah, pal, outT_h, outT_l, bo, h, nullptr, nullptr, DIM, DIM);

        // --- FFN block ---
        layernorm_k<<<TOK, 256>>>(h, g2, bb2, pyh, pyl);
        gemm_mma_k<1><<<dim3(MLPD / 128, TOK / 128), 256, GEMM_SMEM>>>(
            pyh, pyl, w1T_h, w1T_l, bf1, nullptr, pmh, pml, MLPD, DIM);
        gemm_mma_k<2><<<dim3(DIM / 128, TOK / 128), 256, GEMM_SMEM>>>(
            pmh, pml, w2T_h, w2T_l, bf2, h, nullptr, nullptr, DIM, MLPD);
    }
}

// round 6
// speedup vs baseline: 2.6539x; 1.6668x over previous
#include <cuda_runtime.h>
#include <cuda_bf16.h>
#include <math.h>
#include <stdint.h>

#define DIM    1024
#define SEQ    2048
#define BATCH  2
#define TOK    (BATCH*SEQ)   // 4096
#define HEADS  16
#define HD     64
#define MLPD   4096
#define NLAYER 6
#define SCALE  0.03125f
#define EPS    1e-5f

typedef __nv_bfloat16 bf16;

// ---------------- scratch (static device globals; no allocation) ------------
__device__ bf16  g_qkvb[TOK * 3 * DIM];                     // bf16 qkv for attention
__device__ bf16  g_yh[TOK * DIM],  g_yl[TOK * DIM];         // LN out hi/lo
__device__ bf16  g_ah[TOK * DIM],  g_al[TOK * DIM];         // attention out hi/lo
__device__ bf16  g_mh[(size_t)TOK * MLPD], g_ml[(size_t)TOK * MLPD]; // MLP hidden
// transposed+split weights [N,K] bf16, per layer, hi then lo
__device__ bf16  g_wqkvT[2][NLAYER][3 * DIM * DIM];
__device__ bf16  g_woutT[2][NLAYER][DIM * DIM];
__device__ bf16  g_w1T[2][NLAYER][(size_t)DIM * MLPD];
__device__ bf16  g_w2T[2][NLAYER][(size_t)DIM * MLPD];

// ---------------- PTX helpers (sm_80-class only: valid on plain sm_103) -----
__device__ __forceinline__ uint32_t smem_u32(const void* p) {
    uint32_t a;
    asm("{ .reg .u64 t; cvta.to.shared.u64 t, %1; cvt.u32.u64 %0, t; }"
        : "=r"(a) : "l"(p));
    return a;
}
#define LDSM4(r, addr) \
    asm volatile("ldmatrix.sync.aligned.m8n8.x4.shared.b16 {%0,%1,%2,%3}, [%4];" \
        : "=r"((r)[0]), "=r"((r)[1]), "=r"((r)[2]), "=r"((r)[3]) : "r"(addr))
#define LDSM4T(r, addr) \
    asm volatile("ldmatrix.sync.aligned.m8n8.x4.trans.shared.b16 {%0,%1,%2,%3}, [%4];" \
        : "=r"((r)[0]), "=r"((r)[1]), "=r"((r)[2]), "=r"((r)[3]) : "r"(addr))
#define LDSM2(r, addr) \
    asm volatile("ldmatrix.sync.aligned.m8n8.x2.shared.b16 {%0,%1}, [%2];" \
        : "=r"((r)[0]), "=r"((r)[1]) : "r"(addr))
#define MMA16816(d, a, b) \
    asm volatile("mma.sync.aligned.m16n8k16.row.col.f32.bf16.bf16.f32 " \
        "{%0,%1,%2,%3}, {%4,%5,%6,%7}, {%8,%9}, {%0,%1,%2,%3};" \
        : "+f"((d)[0]), "+f"((d)[1]), "+f"((d)[2]), "+f"((d)[3]) \
        : "r"((a)[0]), "r"((a)[1]), "r"((a)[2]), "r"((a)[3]), \
          "r"((b)[0]), "r"((b)[1]))
#define CP_ASYNC16(dst, src) \
    asm volatile("cp.async.cg.shared.global [%0], [%1], 16;" \
        :: "r"(dst), "l"(src) : "memory")
#define CP_COMMIT() asm volatile("cp.async.commit_group;" ::: "memory")
#define CP_WAIT(n)  asm volatile("cp.async.wait_group %0;" :: "n"(n) : "memory")
#define PACK_BF16X2(d, lo, hi) \
    asm("cvt.rn.bf16x2.f32 %0, %1, %2;" : "=r"(d) : "f"(hi), "f"(lo))

__device__ __forceinline__ void split2(float a, float b, uint32_t& hi, uint32_t& lo) {
    __nv_bfloat16 ah = __float2bfloat16(a), bh = __float2bfloat16(b);
    __nv_bfloat162 H, L;
    H.x = ah; H.y = bh;
    L.x = __float2bfloat16(a - __bfloat162float(ah));
    L.y = __float2bfloat16(b - __bfloat162float(bh));
    hi = *(uint32_t*)&H; lo = *(uint32_t*)&L;
}
__device__ __forceinline__ float gelu_exact(float x) {
    return 0.5f * x * (1.0f + erff(x * 0.70710678118654752f));
}

// ---------------- simple copy ------------------------------------------------
__global__ __launch_bounds__(256) void copy_kernel(const float* __restrict__ in,
                                                   float* __restrict__ out) {
    size_t i = (size_t)blockIdx.x * 256 + threadIdx.x;
    ((float4*)out)[i] = ((const float4*)in)[i];
}

// ---------------- weight transpose + bf16 split: W[K,N] -> T{hi,lo}[N,K] ----
__global__ __launch_bounds__(256) void transpose_split_k(const float* __restrict__ W,
                                                         bf16* __restrict__ Thi,
                                                         bf16* __restrict__ Tlo,
                                                         int K, int N) {
    __shared__ float s[32][33];
    int n0 = blockIdx.x * 32, k0 = blockIdx.y * 32;
    int tx = threadIdx.x & 31, ty = threadIdx.x >> 5;   // ty 0..7
#pragma unroll
    for (int i = 0; i < 4; i++)
        s[ty + 8 * i][tx] = W[(size_t)(k0 + ty + 8 * i) * N + n0 + tx];
    __syncthreads();
#pragma unroll
    for (int i = 0; i < 4; i++) {
        float v = s[tx][ty + 8 * i];
        int n = n0 + ty + 8 * i, k = k0 + tx;
        bf16 hi = __float2bfloat16(v);
        Thi[(size_t)n * K + k] = hi;
        Tlo[(size_t)n * K + k] = __float2bfloat16(v - __bfloat162float(hi));
    }
}

// ---------------- layernorm -> split bf16 hi/lo ------------------------------
__global__ __launch_bounds__(256) void layernorm_k(const float* __restrict__ x,
                                                   const float* __restrict__ g,
                                                   const float* __restrict__ b,
                                                   bf16* __restrict__ yh,
                                                   bf16* __restrict__ yl) {
    int row = blockIdx.x;
    int t = threadIdx.x;
    float4 v = ((const float4*)(x + (size_t)row * DIM))[t];
    float s = v.x + v.y + v.z + v.w;
    float ss = v.x * v.x + v.y * v.y + v.z * v.z + v.w * v.w;
#pragma unroll
    for (int off = 16; off; off >>= 1) {
        s  += __shfl_xor_sync(0xffffffffu, s, off);
        ss += __shfl_xor_sync(0xffffffffu, ss, off);
    }
    __shared__ float sh[16];
    int w = t >> 5;
    if ((t & 31) == 0) { sh[w] = s; sh[8 + w] = ss; }
    __syncthreads();
    float S = 0.f, SS = 0.f;
#pragma unroll
    for (int i = 0; i < 8; i++) { S += sh[i]; SS += sh[8 + i]; }
    float mean = S * (1.0f / DIM);
    float var  = SS * (1.0f / DIM) - mean * mean;
    float r = rsqrtf(var + EPS);
    float4 gv = ((const float4*)g)[t];
    float4 bv = ((const float4*)b)[t];
    float o0 = (v.x - mean) * r * gv.x + bv.x;
    float o1 = (v.y - mean) * r * gv.y + bv.y;
    float o2 = (v.z - mean) * r * gv.z + bv.z;
    float o3 = (v.w - mean) * r * gv.w + bv.w;
    uint32_t h0, l0, h1, l1;
    split2(o0, o1, h0, l0); split2(o2, o3, h1, l1);
    *(uint2*)(yh + (size_t)row * DIM + t * 4) = make_uint2(h0, h1);
    *(uint2*)(yl + (size_t)row * DIM + t * 4) = make_uint2(l0, l1);
}

// ---------------- warp-MMA split-bf16 GEMM -----------------------------------
// C[M,N] = A[M,K] @ B^T with B stored [N,K]; A,B as (hi,lo) bf16 pairs.
// CTA tile 128x128, 8 warps (2 in m x 4 in n), warp tile 64x32, mma m16n8k16.
// EPI 0: C fp32 = AB
// EPI 1: gelu(AB + bias) -> Ohi/Olo bf16 split
// EPI 2: C fp32 += AB + bias
// EPI 3: plain bf16 -> Ohi
#define GBK    32                  // K-chunk
#define GSTR   40                  // smem row stride in bf16 (80 B, conflict-free)
#define GTILE  (128 * GSTR * 2)    // 10240 B per tile
#define GSTAGE (4 * GTILE)         // Ahi|Alo|Bhi|Blo = 40960 B
#define GEMM_SMEM (2 * GSTAGE)     // 81920 B

template <int EPI>
__global__ __launch_bounds__(256, 1) void gemm_mma_k(
    const bf16* __restrict__ Ahi, const bf16* __restrict__ Alo,
    const bf16* __restrict__ Bhi, const bf16* __restrict__ Blo,
    const float* __restrict__ bias, float* __restrict__ C,
    bf16* __restrict__ Ohi, bf16* __restrict__ Olo,
    int N, int K) {
    extern __shared__ __align__(1024) char smem[];
    uint32_t sb = smem_u32(smem);
    int tid = threadIdx.x;
    int lane = tid & 31, wid = tid >> 5;
    int wm = wid & 1, wn = wid >> 1;          // warp grid 2 x 4
    int bm = blockIdx.y * 128, bn = blockIdx.x * 128;

    int matA = lane >> 3;                      // 0..3
    int rowA = wm * 64 + (matA & 1) * 8 + (lane & 7);
    int colA = (matA >> 1) * 8;
    uint32_t offA0 = (uint32_t)((rowA * GSTR + colA) * 2);
    int lb = lane & 15;
    int rowB = wn * 32 + (lb & 7);
    int colB = (lb >> 3) * 8;
    uint32_t offB0 = (uint32_t)((rowB * GSTR + colB) * 2) + 2 * (uint32_t)GTILE;

    float acc[4][4][4];
#pragma unroll
    for (int i = 0; i < 4; i++)
#pragma unroll
        for (int j = 0; j < 4; j++)
#pragma unroll
            for (int r = 0; r < 4; r++) acc[i][j][r] = 0.f;

    auto issue = [&](int s, int kc) {
        uint32_t stoff = sb + s * GSTAGE;
#pragma unroll
        for (int it = 0; it < 8; ++it) {
            int idx = it * 256 + tid;
            int tl = it >> 1;
            int j = idx & 511;
            int r = j >> 2;
            int c = j & 3;
            const bf16* src = (tl == 0) ? Ahi : (tl == 1) ? Alo
                            : (tl == 2) ? Bhi : Blo;
            int row0 = (tl < 2) ? bm : bn;
            const bf16* gp = src + (size_t)(row0 + r) * K + kc + c * 8;
            uint32_t dp = stoff + tl * GTILE + (uint32_t)((r * GSTR + c * 8) * 2);
            CP_ASYNC16(dp, gp);
        }
    };

    issue(0, 0);
    CP_COMMIT();

    const int NC = K / GBK;
    for (int c = 0; c < NC; ++c) {
        if (c + 1 < NC) {
            issue((c + 1) & 1, (c + 1) * GBK);
            CP_COMMIT();
            CP_WAIT(1);
        } else {
            CP_WAIT(0);
        }
        __syncthreads();

        uint32_t st = sb + (c & 1) * GSTAGE;
#pragma unroll
        for (int kk = 0; kk < 2; ++kk) {
            uint32_t kb = st + kk * 32;
            uint32_t a[4][2][4], b[4][2][2];
#pragma unroll
            for (int i = 0; i < 4; i++) {
                LDSM4(a[i][0], kb + offA0 + i * (16 * GSTR * 2));
                LDSM4(a[i][1], kb + offA0 + i * (16 * GSTR * 2) + GTILE);
            }
#pragma unroll
            for (int j = 0; j < 4; j++) {
                LDSM2(b[j][0], kb + offB0 + j * (8 * GSTR * 2));
                LDSM2(b[j][1], kb + offB0 + j * (8 * GSTR * 2) + GTILE);
            }
#pragma unroll
            for (int i = 0; i < 4; i++)
#pragma unroll
                for (int j = 0; j < 4; j++) {
                    MMA16816(acc[i][j], a[i][0], b[j][0]);
                    MMA16816(acc[i][j], a[i][0], b[j][1]);
                    MMA16816(acc[i][j], a[i][1], b[j][0]);
                }
        }
        __syncthreads();
    }

    int g = lane >> 2, tg = (lane & 3) * 2;
#pragma unroll
    for (int i = 0; i < 4; i++) {
        int row = bm + wm * 64 + i * 16 + g;
#pragma unroll
        for (int j = 0; j < 4; j++) {
            int col = bn + wn * 32 + j * 8 + tg;
#pragma unroll
            for (int half = 0; half < 2; half++) {
                int rr = row + half * 8;
                float v0 = acc[i][j][half * 2 + 0];
                float v1 = acc[i][j][half * 2 + 1];
                if (EPI == 0) {
                    *(float2*)(C + (size_t)rr * N + col) = make_float2(v0, v1);
                } else if (EPI == 1) {
                    float a0 = gelu_exact(v0 + __ldg(bias + col));
                    float a1 = gelu_exact(v1 + __ldg(bias + col + 1));
                    uint32_t hi, lo;
                    split2(a0, a1, hi, lo);
                    *(uint32_t*)(Ohi + (size_t)rr * N + col) = hi;
                    *(uint32_t*)(Olo + (size_t)rr * N + col) = lo;
                } else if (EPI == 2) {
                    float2 old = *(float2*)(C + (size_t)rr * N + col);
                    old.x += v0 + __ldg(bias + col);
                    old.y += v1 + __ldg(bias + col + 1);
                    *(float2*)(C + (size_t)rr * N + col) = old;
                } else {
                    uint32_t p;
                    PACK_BF16X2(p, v0, v1);
                    *(uint32_t*)(Ohi + (size_t)rr * N + col) = p;
                }
            }
        }
    }
}

// ---------------- MMA flash attention (bf16 tensor, fp32 softmax) ------------
// CTA: 128 queries x one (batch, head). 8 warps, each owns 16 query rows x all
// 64 keys of the tile. Q/K/V bf16 from g_qkvb [tok, 3*DIM].
#define AKPAD  72                          // smem row stride (bf16); 144B rows
#define AQ_BYTES (128 * AKPAD * 2)         // 18432
#define AKV_BYTES (64 * AKPAD * 2)         // 9216
// layout: Q | K0 | V0 | K1 | V1
#define ATTM_SMEM (AQ_BYTES + 4 * AKV_BYTES)   // 55296

__global__ __launch_bounds__(256, 1) void attn_mma_k(const bf16* __restrict__ qkv,
                                                     bf16* __restrict__ oh,
                                                     bf16* __restrict__ ol) {
    extern __shared__ __align__(1024) char smem[];
    uint32_t sb = smem_u32(smem);
    int tid = threadIdx.x;
    int lane = tid & 31, wid = tid >> 5;
    int q0 = blockIdx.x * 128;
    int hh = blockIdx.y;
    int bb = blockIdx.z;

    const size_t rstr = 3 * DIM;
    const bf16* base = qkv + (size_t)(bb * SEQ) * rstr + hh * HD;

    // --- load Q tile [128 x 64] via cp.async ---
    {
#pragma unroll
        for (int it = 0; it < 4; ++it) {
            int idx = it * 256 + tid;
            int r = idx >> 3, c = idx & 7;
            CP_ASYNC16(sb + (uint32_t)(r * AKPAD + c * 8) * 2,
                       base + (size_t)(q0 + r) * rstr + c * 8);
        }
    }
    // --- K/V tile loader into buffer s ---
    auto issueKV = (void(*)())nullptr; (void)issueKV;
    auto loadKV = [&](int s, int kt) {
        uint32_t kbuf = sb + AQ_BYTES + (uint32_t)(2 * s) * AKV_BYTES;
        uint32_t vbuf = kbuf + AKV_BYTES;
#pragma unroll
        for (int it = 0; it < 2; ++it) {
            int idx = it * 256 + tid;
            int r = idx >> 3, c = idx & 7;
            const bf16* kp = base + DIM + (size_t)(kt * 64 + r) * rstr + c * 8;
            const bf16* vp = base + 2 * DIM + (size_t)(kt * 64 + r) * rstr + c * 8;
            uint32_t off = (uint32_t)(r * AKPAD + c * 8) * 2;
            CP_ASYNC16(kbuf + off, kp);
            CP_ASYNC16(vbuf + off, vp);
        }
    };

    loadKV(0, 0);
    CP_COMMIT();

    // ldmatrix lane offsets
    int wq0 = wid * 16;
    uint32_t offQ = (uint32_t)(((wq0 + ((lane >> 3) & 1) * 8 + (lane & 7)) * AKPAD
                               + (lane >> 4) * 8) * 2);
    uint32_t offK = (uint32_t)((((lane & 7) + (lane >> 4) * 8) * AKPAD
                               + ((lane >> 3) & 1) * 8) * 2);
    uint32_t offV = (uint32_t)((((lane & 7) + ((lane >> 3) & 1) * 8) * AKPAD
                               + (lane >> 4) * 8) * 2);

    float accO[8][4];
#pragma unroll
    for (int j = 0; j < 8; j++)
#pragma unroll
        for (int r = 0; r < 4; r++) accO[j][r] = 0.f;
    float m0 = -1e30f, m1 = -1e30f, l0 = 0.f, l1 = 0.f;

    uint32_t aQ[4][4];
    bool qLoaded = false;

    const int NT = SEQ / 64;
    for (int kt = 0; kt < NT; ++kt) {
        if (kt + 1 < NT) {
            loadKV((kt + 1) & 1, kt + 1);
            CP_COMMIT();
            CP_WAIT(1);
        } else {
            CP_WAIT(0);
        }
        __syncthreads();

        if (!qLoaded) {   // Q resident after first wait
#pragma unroll
            for (int k = 0; k < 4; k++) LDSM4(aQ[k], sb + offQ + k * 32);
            qLoaded = true;
        }

        uint32_t kbuf = sb + AQ_BYTES + (uint32_t)(2 * (kt & 1)) * AKV_BYTES;
        uint32_t vbuf = kbuf + AKV_BYTES;

        // ---- S = Q @ K^T : 8 n-tiles of 8 keys ----
        float accS[8][4];
#pragma unroll
        for (int j = 0; j < 8; j++)
#pragma unroll
            for (int r = 0; r < 4; r++) accS[j][r] = 0.f;
#pragma unroll
        for (int j2 = 0; j2 < 4; j2++) {
            uint32_t kb = kbuf + offK + (uint32_t)(j2 * 16 * AKPAD * 2);
#pragma unroll
            for (int kk = 0; kk < 4; kk++) {
                uint32_t b[4];
                LDSM4(b, kb + kk * 32);
                MMA16816(accS[j2 * 2],     aQ[kk], (b));
                MMA16816(accS[j2 * 2 + 1], aQ[kk], (b + 2));
            }
        }

        // ---- online softmax (rows r=lane>>2 in c0/c1, r+8 in c2/c3) ----
        float mx0 = -1e30f, mx1 = -1e30f;
#pragma unroll
        for (int j = 0; j < 8; j++) {
            accS[j][0] *= SCALE; accS[j][1] *= SCALE;
            accS[j][2] *= SCALE; accS[j][3] *= SCALE;
            mx0 = fmaxf(mx0, fmaxf(accS[j][0], accS[j][1]));
            mx1 = fmaxf(mx1, fmaxf(accS[j][2], accS[j][3]));
        }
#pragma unroll
        for (int off = 1; off <= 2; off <<= 1) {
            mx0 = fmaxf(mx0, __shfl_xor_sync(0xffffffffu, mx0, off));
            mx1 = fmaxf(mx1, __shfl_xor_sync(0xffffffffu, mx1, off));
        }
        float nm0 = fmaxf(m0, mx0), nm1 = fmaxf(m1, mx1);
        float al0 = __expf(m0 - nm0), al1 = __expf(m1 - nm1);
        m0 = nm0; m1 = nm1;
        float ps0 = 0.f, ps1 = 0.f;
#pragma unroll
        for (int j = 0; j < 8; j++) {
            accS[j][0] = __expf(accS[j][0] - nm0);
            accS[j][1] = __expf(accS[j][1] - nm0);
            accS[j][2] = __expf(accS[j][2] - nm1);
            accS[j][3] = __expf(accS[j][3] - nm1);
            ps0 += accS[j][0] + accS[j][1];
            ps1 += accS[j][2] + accS[j][3];
        }
#pragma unroll
        for (int off = 1; off <= 2; off <<= 1) {
            ps0 += __shfl_xor_sync(0xffffffffu, ps0, off);
            ps1 += __shfl_xor_sync(0xffffffffu, ps1, off);
        }
        l0 = l0 * al0 + ps0;
        l1 = l1 * al1 + ps1;
#pragma unroll
        for (int j = 0; j < 8; j++) {
            accO[j][0] *= al0; accO[j][1] *= al0;
            accO[j][2] *= al1; accO[j][3] *= al1;
        }

        // ---- P -> A fragments (register repack) ----
        uint32_t aP[4][4];
#pragma unroll
        for (int kk = 0; kk < 4; kk++) {
            PACK_BF16X2(aP[kk][0], accS[2 * kk][0],     accS[2 * kk][1]);
            PACK_BF16X2(aP[kk][1], accS[2 * kk][2],     accS[2 * kk][3]);
            PACK_BF16X2(aP[kk][2], accS[2 * kk + 1][0], accS[2 * kk + 1][1]);
            PACK_BF16X2(aP[kk][3], accS[2 * kk + 1][2], accS[2 * kk + 1][3]);
        }

        // ---- O += P @ V : V via ldmatrix trans ----
#pragma unroll
        for (int j2 = 0; j2 < 4; j2++) {
            uint32_t vb0 = vbuf + offV + (uint32_t)(j2 * 16 * 2);
#pragma unroll
            for (int kk = 0; kk < 4; kk++) {
                uint32_t b[4];
                LDSM4T(b, vb0 + (uint32_t)(kk * 16 * AKPAD * 2));
                MMA16816(accO[j2 * 2],     aP[kk], (b));
                MMA16816(accO[j2 * 2 + 1], aP[kk], (b + 2));
            }
        }
        __syncthreads();
    }

    // ---- finalize, write split hi/lo ----
    float inv0 = 1.0f / l0, inv1 = 1.0f / l1;
    int r0 = q0 + wq0 + (lane >> 2);
    int cbase = hh * HD + (lane & 3) * 2;
#pragma unroll
    for (int j = 0; j < 8; j++) {
        int col = cbase + j * 8;
        uint32_t hi, lo;
        split2(accO[j][0] * inv0, accO[j][1] * inv0, hi, lo);
        size_t idx = (size_t)(bb * SEQ + r0) * DIM + col;
        *(uint32_t*)(oh + idx) = hi;
        *(uint32_t*)(ol + idx) = lo;
        split2(accO[j][2] * inv1, accO[j][3] * inv1, hi, lo);
        idx = (size_t)(bb * SEQ + r0 + 8) * DIM + col;
        *(uint32_t*)(oh + idx) = hi;
        *(uint32_t*)(ol + idx) = lo;
    }
}

// ---------------- driver -----------------------------------------------------
extern "C" void kernel_launch(void* const* d_in, const int* in_sizes, int n_in,
                              void* d_out, int out_size) {
    const float* x    = (const float*)d_in[0];
    const float* Wqkv = (const float*)d_in[1];
    const float* Wout = (const float*)d_in[2];
    const float* bout = (const float*)d_in[3];
    const float* ln1g = (const float*)d_in[4];
    const float* ln1b = (const float*)d_in[5];
    const float* ln2g = (const float*)d_in[6];
    const float* ln2b = (const float*)d_in[7];
    const float* W1   = (const float*)d_in[8];
    const float* b1   = (const float*)d_in[9];
    const float* W2   = (const float*)d_in[10];
    const float* b2   = (const float*)d_in[11];

    float* h = (float*)d_out;

    bf16 *pqkvb, *pyh, *pyl, *pah, *pal, *pmh, *pml;
    bf16 *pwqkvT, *pwoutT, *pw1T, *pw2T;
    cudaGetSymbolAddress((void**)&pqkvb,  g_qkvb);
    cudaGetSymbolAddress((void**)&pyh,    g_yh);
    cudaGetSymbolAddress((void**)&pyl,    g_yl);
    cudaGetSymbolAddress((void**)&pah,    g_ah);
    cudaGetSymbolAddress((void**)&pal,    g_al);
    cudaGetSymbolAddress((void**)&pmh,    g_mh);
    cudaGetSymbolAddress((void**)&pml,    g_ml);
    cudaGetSymbolAddress((void**)&pwqkvT, g_wqkvT);
    cudaGetSymbolAddress((void**)&pwoutT, g_woutT);
    cudaGetSymbolAddress((void**)&pw1T,   g_w1T);
    cudaGetSymbolAddress((void**)&pw2T,   g_w2T);

    cudaFuncSetAttribute(attn_mma_k, cudaFuncAttributeMaxDynamicSharedMemorySize, ATTM_SMEM);
    cudaFuncSetAttribute(gemm_mma_k<1>, cudaFuncAttributeMaxDynamicSharedMemorySize, GEMM_SMEM);
    cudaFuncSetAttribute(gemm_mma_k<2>, cudaFuncAttributeMaxDynamicSharedMemorySize, GEMM_SMEM);
    cudaFuncSetAttribute(gemm_mma_k<3>, cudaFuncAttributeMaxDynamicSharedMemorySize, GEMM_SMEM);

    const size_t SZ_QKV = (size_t)3 * DIM * DIM;
    const size_t SZ_OUT = (size_t)DIM * DIM;
    const size_t SZ_MLP = (size_t)DIM * MLPD;

    for (int l = 0; l < NLAYER; l++) {
        transpose_split_k<<<dim3(3 * DIM / 32, DIM / 32), 256>>>(
            Wqkv + (size_t)l * SZ_QKV,
            pwqkvT + (size_t)l * SZ_QKV, pwqkvT + ((size_t)NLAYER + l) * SZ_QKV,
            DIM, 3 * DIM);
        transpose_split_k<<<dim3(DIM / 32, DIM / 32), 256>>>(
            Wout + (size_t)l * SZ_OUT,
            pwoutT + (size_t)l * SZ_OUT, pwoutT + ((size_t)NLAYER + l) * SZ_OUT,
            DIM, DIM);
        transpose_split_k<<<dim3(MLPD / 32, DIM / 32), 256>>>(
            W1 + (size_t)l * SZ_MLP,
            pw1T + (size_t)l * SZ_MLP, pw1T + ((size_t)NLAYER + l) * SZ_MLP,
            DIM, MLPD);
        transpose_split_k<<<dim3(DIM / 32, MLPD / 32), 256>>>(
            W2 + (size_t)l * SZ_MLP,
            pw2T + (size_t)l * SZ_MLP, pw2T + ((size_t)NLAYER + l) * SZ_MLP,
            MLPD, DIM);
    }

    copy_kernel<<<TOK * DIM / (256 * 4), 256>>>(x, h);

    for (int l = 0; l < NLAYER; l++) {
        const float* bo  = bout + (size_t)l * DIM;
        const float* g1  = ln1g + (size_t)l * DIM;
        const float* bb1 = ln1b + (size_t)l * DIM;
        const float* g2  = ln2g + (size_t)l * DIM;
        const float* bb2 = ln2b + (size_t)l * DIM;
        const float* bf1 = b1 + (size_t)l * MLPD;
        const float* bf2 = b2 + (size_t)l * DIM;

        bf16* qkvT_h = pwqkvT + (size_t)l * SZ_QKV;
        bf16* qkvT_l = pwqkvT + ((size_t)NLAYER + l) * SZ_QKV;
        bf16* outT_h = pwoutT + (size_t)l * SZ_OUT;
        bf16* outT_l = pwoutT + ((size_t)NLAYER + l) * SZ_OUT;
        bf16* w1T_h  = pw1T + (size_t)l * SZ_MLP;
        bf16* w1T_l  = pw1T + ((size_t)NLAYER + l) * SZ_MLP;
        bf16* w2T_h  = pw2T + (size_t)l * SZ_MLP;
        bf16* w2T_l  = pw2T + ((size_t)NLAYER + l) * SZ_MLP;

        // --- attention block ---
        layernorm_k<<<TOK, 256>>>(h, g1, bb1, pyh, pyl);
        gemm_mma_k<3><<<dim3(3 * DIM / 128, TOK / 128), 256, GEMM_SMEM>>>(
            pyh, pyl, qkvT_h, qkvT_l, nullptr, nullptr, pqkvb, nullptr, 3 * DIM, DIM);
        attn_mma_k<<<dim3(SEQ / 128, HEADS, BATCH), 256, ATTM_SMEM>>>(pqkvb, pah, pal);
        gemm_mma_k<2><<<dim3(DIM / 128, TOK / 128), 256, GEMM_SMEM>>>(
            pah, pal, outT_h, outT_l, bo, h, nullptr, nullptr, DIM, DIM);

        // --- FFN block ---
        layernorm_k<<<TOK, 256>>>(h, g2, bb2, pyh, pyl);
        gemm_mma_k<1><<<dim3(MLPD / 128, TOK / 128), 256, GEMM_SMEM>>>(
            pyh, pyl, w1T_h, w1T_l, bf1, nullptr, pmh, pml, MLPD, DIM);
        gemm_mma_k<2><<<dim3(DIM / 128, TOK / 128), 256, GEMM_SMEM>>>(
            pmh, pml, w2T_h, w2T_l, bf2, h, nullptr, nullptr, DIM, MLPD);
    }
}

// round 7
// speedup vs baseline: 2.7968x; 1.0539x over previous
#include <cuda_runtime.h>
#include <cuda_bf16.h>
#include <math.h>
#include <stdint.h>

#define DIM    1024
#define SEQ    2048
#define BATCH  2
#define TOK    (BATCH*SEQ)   // 4096
#define HEADS  16
#define HD     64
#define MLPD   4096
#define NLAYER 6
#define SCALE  0.03125f
#define EPS    1e-5f

typedef __nv_bfloat16 bf16;

// ---------------- scratch (static device globals; no allocation) ------------
__device__ bf16  g_qkvb[TOK * 3 * DIM];                     // bf16 qkv for attention
__device__ bf16  g_yh[TOK * DIM],  g_yl[TOK * DIM];         // LN out hi/lo
__device__ bf16  g_ah[TOK * DIM],  g_al[TOK * DIM];         // attention out hi/lo
__device__ bf16  g_mh[(size_t)TOK * MLPD], g_ml[(size_t)TOK * MLPD]; // MLP hidden
// transposed+split weights [N,K] bf16, per layer, hi then lo
__device__ bf16  g_wqkvT[2][NLAYER][3 * DIM * DIM];
__device__ bf16  g_woutT[2][NLAYER][DIM * DIM];
__device__ bf16  g_w1T[2][NLAYER][(size_t)DIM * MLPD];
__device__ bf16  g_w2T[2][NLAYER][(size_t)DIM * MLPD];

// ---------------- PTX helpers (sm_80-class only: valid on plain sm_103) -----
__device__ __forceinline__ uint32_t smem_u32(const void* p) {
    uint32_t a;
    asm("{ .reg .u64 t; cvta.to.shared.u64 t, %1; cvt.u32.u64 %0, t; }"
        : "=r"(a) : "l"(p));
    return a;
}
#define LDSM4(r, addr) \
    asm volatile("ldmatrix.sync.aligned.m8n8.x4.shared.b16 {%0,%1,%2,%3}, [%4];" \
        : "=r"((r)[0]), "=r"((r)[1]), "=r"((r)[2]), "=r"((r)[3]) : "r"(addr))
#define LDSM4T(r, addr) \
    asm volatile("ldmatrix.sync.aligned.m8n8.x4.trans.shared.b16 {%0,%1,%2,%3}, [%4];" \
        : "=r"((r)[0]), "=r"((r)[1]), "=r"((r)[2]), "=r"((r)[3]) : "r"(addr))
#define MMA16816(d, a, b) \
    asm volatile("mma.sync.aligned.m16n8k16.row.col.f32.bf16.bf16.f32 " \
        "{%0,%1,%2,%3}, {%4,%5,%6,%7}, {%8,%9}, {%0,%1,%2,%3};" \
        : "+f"((d)[0]), "+f"((d)[1]), "+f"((d)[2]), "+f"((d)[3]) \
        : "r"((a)[0]), "r"((a)[1]), "r"((a)[2]), "r"((a)[3]), \
          "r"((b)[0]), "r"((b)[1]))
#define CP_ASYNC16(dst, src) \
    asm volatile("cp.async.cg.shared.global [%0], [%1], 16;" \
        :: "r"(dst), "l"(src) : "memory")
#define CP_COMMIT() asm volatile("cp.async.commit_group;" ::: "memory")
#define CP_WAIT(n)  asm volatile("cp.async.wait_group %0;" :: "n"(n) : "memory")
#define PACK_BF16X2(d, lo, hi) \
    asm("cvt.rn.bf16x2.f32 %0, %1, %2;" : "=r"(d) : "f"(hi), "f"(lo))

__device__ __forceinline__ void split2(float a, float b, uint32_t& hi, uint32_t& lo) {
    __nv_bfloat16 ah = __float2bfloat16(a), bh = __float2bfloat16(b);
    __nv_bfloat162 H, L;
    H.x = ah; H.y = bh;
    L.x = __float2bfloat16(a - __bfloat162float(ah));
    L.y = __float2bfloat16(b - __bfloat162float(bh));
    hi = *(uint32_t*)&H; lo = *(uint32_t*)&L;
}
__device__ __forceinline__ float gelu_exact(float x) {
    return 0.5f * x * (1.0f + erff(x * 0.70710678118654752f));
}

// ---------------- simple copy ------------------------------------------------
__global__ __launch_bounds__(256) void copy_kernel(const float* __restrict__ in,
                                                   float* __restrict__ out) {
    size_t i = (size_t)blockIdx.x * 256 + threadIdx.x;
    ((float4*)out)[i] = ((const float4*)in)[i];
}

// ---------------- weight transpose + bf16 split: W[K,N] -> T{hi,lo}[N,K] ----
__global__ __launch_bounds__(256) void transpose_split_k(const float* __restrict__ W,
                                                         bf16* __restrict__ Thi,
                                                         bf16* __restrict__ Tlo,
                                                         int K, int N) {
    __shared__ float s[32][33];
    int n0 = blockIdx.x * 32, k0 = blockIdx.y * 32;
    int tx = threadIdx.x & 31, ty = threadIdx.x >> 5;   // ty 0..7
#pragma unroll
    for (int i = 0; i < 4; i++)
        s[ty + 8 * i][tx] = W[(size_t)(k0 + ty + 8 * i) * N + n0 + tx];
    __syncthreads();
#pragma unroll
    for (int i = 0; i < 4; i++) {
        float v = s[tx][ty + 8 * i];
        int n = n0 + ty + 8 * i, k = k0 + tx;
        bf16 hi = __float2bfloat16(v);
        Thi[(size_t)n * K + k] = hi;
        Tlo[(size_t)n * K + k] = __float2bfloat16(v - __bfloat162float(hi));
    }
}

// ---------------- layernorm -> split bf16 hi/lo ------------------------------
__global__ __launch_bounds__(256) void layernorm_k(const float* __restrict__ x,
                                                   const float* __restrict__ g,
                                                   const float* __restrict__ b,
                                                   bf16* __restrict__ yh,
                                                   bf16* __restrict__ yl) {
    int row = blockIdx.x;
    int t = threadIdx.x;
    float4 v = ((const float4*)(x + (size_t)row * DIM))[t];
    float s = v.x + v.y + v.z + v.w;
    float ss = v.x * v.x + v.y * v.y + v.z * v.z + v.w * v.w;
#pragma unroll
    for (int off = 16; off; off >>= 1) {
        s  += __shfl_xor_sync(0xffffffffu, s, off);
        ss += __shfl_xor_sync(0xffffffffu, ss, off);
    }
    __shared__ float sh[16];
    int w = t >> 5;
    if ((t & 31) == 0) { sh[w] = s; sh[8 + w] = ss; }
    __syncthreads();
    float S = 0.f, SS = 0.f;
#pragma unroll
    for (int i = 0; i < 8; i++) { S += sh[i]; SS += sh[8 + i]; }
    float mean = S * (1.0f / DIM);
    float var  = SS * (1.0f / DIM) - mean * mean;
    float r = rsqrtf(var + EPS);
    float4 gv = ((const float4*)g)[t];
    float4 bv = ((const float4*)b)[t];
    float o0 = (v.x - mean) * r * gv.x + bv.x;
    float o1 = (v.y - mean) * r * gv.y + bv.y;
    float o2 = (v.z - mean) * r * gv.z + bv.z;
    float o3 = (v.w - mean) * r * gv.w + bv.w;
    uint32_t h0, l0, h1, l1;
    split2(o0, o1, h0, l0); split2(o2, o3, h1, l1);
    *(uint2*)(yh + (size_t)row * DIM + t * 4) = make_uint2(h0, h1);
    *(uint2*)(yl + (size_t)row * DIM + t * 4) = make_uint2(l0, l1);
}

// ---------------- warp-MMA split-bf16 GEMM -----------------------------------
// C[M,N] = A[M,K] @ B^T with B stored [N,K]; A,B as (hi,lo) bf16 pairs.
// CTA tile 128x256, 8 warps (2 in m x 4 in n), warp tile 64x64, mma m16n8k16.
// EPI 0: C fp32 = AB
// EPI 1: gelu(AB + bias) -> Ohi/Olo bf16 split
// EPI 2: C fp32 += AB + bias
// EPI 3: plain bf16 -> Ohi
#define GBK    32                  // K-chunk
#define GSTR   40                  // smem row stride in bf16 (80 B, conflict-free)
#define ATILE  (128 * GSTR * 2)    // 10240 B per A tile
#define BTILE  (256 * GSTR * 2)    // 20480 B per B tile
#define GSTAGE (2 * ATILE + 2 * BTILE)   // Ahi|Alo|Bhi|Blo = 61440 B
#define GEMM_SMEM (2 * GSTAGE)     // 122880 B

template <int EPI>
__global__ __launch_bounds__(256, 1) void gemm_mma_k(
    const bf16* __restrict__ Ahi, const bf16* __restrict__ Alo,
    const bf16* __restrict__ Bhi, const bf16* __restrict__ Blo,
    const float* __restrict__ bias, float* __restrict__ C,
    bf16* __restrict__ Ohi, bf16* __restrict__ Olo,
    int N, int K) {
    extern __shared__ __align__(1024) char smem[];
    uint32_t sb = smem_u32(smem);
    int tid = threadIdx.x;
    int lane = tid & 31, wid = tid >> 5;
    int wm = wid & 1, wn = wid >> 1;          // warp grid 2 (m) x 4 (n)
    int bm = blockIdx.y * 128, bn = blockIdx.x * 256;

    // A ldmatrix lane offset (within an A tile): proven R4 mapping
    int matA = lane >> 3;                      // 0..3
    int rowA = wm * 64 + (matA & 1) * 8 + (lane & 7);
    int colA = (matA >> 1) * 8;
    uint32_t offA0 = (uint32_t)((rowA * GSTR + colA) * 2);
    // B ldmatrix lane offset (LDSM4 = two adjacent n8-tiles x two k8 halves)
    int rowB = wn * 64 + ((lane >> 4) & 1) * 8 + (lane & 7);
    int colB = ((lane >> 3) & 1) * 8;
    uint32_t offB0 = (uint32_t)((rowB * GSTR + colB) * 2) + 2 * (uint32_t)ATILE;

    float acc[4][8][4];
#pragma unroll
    for (int i = 0; i < 4; i++)
#pragma unroll
        for (int j = 0; j < 8; j++)
#pragma unroll
            for (int r = 0; r < 4; r++) acc[i][j][r] = 0.f;

    auto issue = [&](int s, int kc) {
        uint32_t stoff = sb + s * GSTAGE;
        // A tiles: 2 x 512 transfers
#pragma unroll
        for (int it = 0; it < 4; ++it) {
            int idx = it * 256 + tid;
            int tl = idx >> 9;                 // uniform per it
            int j = idx & 511;
            int r = j >> 2, c = j & 3;
            const bf16* src = tl ? Alo : Ahi;
            CP_ASYNC16(stoff + (uint32_t)tl * ATILE + (uint32_t)((r * GSTR + c * 8) * 2),
                       src + (size_t)(bm + r) * K + kc + c * 8);
        }
        // B tiles: 2 x 1024 transfers
#pragma unroll
        for (int it = 0; it < 8; ++it) {
            int idx = it * 256 + tid;
            int tl = idx >> 10;                // uniform per it
            int j = idx & 1023;
            int r = j >> 2, c = j & 3;
            const bf16* src = tl ? Blo : Bhi;
            CP_ASYNC16(stoff + 2 * (uint32_t)ATILE + (uint32_t)tl * BTILE
                           + (uint32_t)((r * GSTR + c * 8) * 2),
                       src + (size_t)(bn + r) * K + kc + c * 8);
        }
    };

    issue(0, 0);
    CP_COMMIT();

    const int NC = K / GBK;
    for (int c = 0; c < NC; ++c) {
        if (c + 1 < NC) {
            issue((c + 1) & 1, (c + 1) * GBK);
            CP_COMMIT();
            CP_WAIT(1);
        } else {
            CP_WAIT(0);
        }
        __syncthreads();

        uint32_t st = sb + (c & 1) * GSTAGE;
#pragma unroll
        for (int kk = 0; kk < 2; ++kk) {
            uint32_t kb = st + kk * 32;
            uint32_t aH[4][4], aL[4][4], bH[4][4], bL[4][4];
#pragma unroll
            for (int i = 0; i < 4; i++) {
                LDSM4(aH[i], kb + offA0 + i * (16 * GSTR * 2));
                LDSM4(aL[i], kb + offA0 + i * (16 * GSTR * 2) + ATILE);
            }
#pragma unroll
            for (int j = 0; j < 4; j++) {
                LDSM4(bH[j], kb + offB0 + j * (16 * GSTR * 2));
                LDSM4(bL[j], kb + offB0 + j * (16 * GSTR * 2) + BTILE);
            }
#pragma unroll
            for (int i = 0; i < 4; i++)
#pragma unroll
                for (int j = 0; j < 4; j++) {
                    MMA16816(acc[i][2 * j],     aH[i], (bH[j]));
                    MMA16816(acc[i][2 * j + 1], aH[i], (bH[j] + 2));
                    MMA16816(acc[i][2 * j],     aH[i], (bL[j]));
                    MMA16816(acc[i][2 * j + 1], aH[i], (bL[j] + 2));
                    MMA16816(acc[i][2 * j],     aL[i], (bH[j]));
                    MMA16816(acc[i][2 * j + 1], aL[i], (bH[j] + 2));
                }
        }
        __syncthreads();
    }

    int g = lane >> 2, tg = (lane & 3) * 2;
#pragma unroll
    for (int i = 0; i < 4; i++) {
        int row = bm + wm * 64 + i * 16 + g;
#pragma unroll
        for (int j = 0; j < 8; j++) {
            int col = bn + wn * 64 + j * 8 + tg;
#pragma unroll
            for (int half = 0; half < 2; half++) {
                int rr = row + half * 8;
                float v0 = acc[i][j][half * 2 + 0];
                float v1 = acc[i][j][half * 2 + 1];
                if (EPI == 0) {
                    *(float2*)(C + (size_t)rr * N + col) = make_float2(v0, v1);
                } else if (EPI == 1) {
                    float a0 = gelu_exact(v0 + __ldg(bias + col));
                    float a1 = gelu_exact(v1 + __ldg(bias + col + 1));
                    uint32_t hi, lo;
                    split2(a0, a1, hi, lo);
                    *(uint32_t*)(Ohi + (size_t)rr * N + col) = hi;
                    *(uint32_t*)(Olo + (size_t)rr * N + col) = lo;
                } else if (EPI == 2) {
                    float2 old = *(float2*)(C + (size_t)rr * N + col);
                    old.x += v0 + __ldg(bias + col);
                    old.y += v1 + __ldg(bias + col + 1);
                    *(float2*)(C + (size_t)rr * N + col) = old;
                } else {
                    uint32_t p;
                    PACK_BF16X2(p, v0, v1);
                    *(uint32_t*)(Ohi + (size_t)rr * N + col) = p;
                }
            }
        }
    }
}

// ---------------- MMA flash attention (bf16 tensor, fp32 softmax) ------------
#define AKPAD  72                          // smem row stride (bf16); 144B rows
#define AQ_BYTES (128 * AKPAD * 2)         // 18432
#define AKV_BYTES (64 * AKPAD * 2)         // 9216
#define ATTM_SMEM (AQ_BYTES + 4 * AKV_BYTES)   // 55296

__global__ __launch_bounds__(256, 1) void attn_mma_k(const bf16* __restrict__ qkv,
                                                     bf16* __restrict__ oh,
                                                     bf16* __restrict__ ol) {
    extern __shared__ __align__(1024) char smem[];
    uint32_t sb = smem_u32(smem);
    int tid = threadIdx.x;
    int lane = tid & 31, wid = tid >> 5;
    int q0 = blockIdx.x * 128;
    int hh = blockIdx.y;
    int bb = blockIdx.z;

    const size_t rstr = 3 * DIM;
    const bf16* base = qkv + (size_t)(bb * SEQ) * rstr + hh * HD;

    {
#pragma unroll
        for (int it = 0; it < 4; ++it) {
            int idx = it * 256 + tid;
            int r = idx >> 3, c = idx & 7;
            CP_ASYNC16(sb + (uint32_t)(r * AKPAD + c * 8) * 2,
                       base + (size_t)(q0 + r) * rstr + c * 8);
        }
    }
    auto loadKV = [&](int s, int kt) {
        uint32_t kbuf = sb + AQ_BYTES + (uint32_t)(2 * s) * AKV_BYTES;
        uint32_t vbuf = kbuf + AKV_BYTES;
#pragma unroll
        for (int it = 0; it < 2; ++it) {
            int idx = it * 256 + tid;
            int r = idx >> 3, c = idx & 7;
            const bf16* kp = base + DIM + (size_t)(kt * 64 + r) * rstr + c * 8;
            const bf16* vp = base + 2 * DIM + (size_t)(kt * 64 + r) * rstr + c * 8;
            uint32_t off = (uint32_t)(r * AKPAD + c * 8) * 2;
            CP_ASYNC16(kbuf + off, kp);
            CP_ASYNC16(vbuf + off, vp);
        }
    };

    loadKV(0, 0);
    CP_COMMIT();

    int wq0 = wid * 16;
    uint32_t offQ = (uint32_t)(((wq0 + ((lane >> 3) & 1) * 8 + (lane & 7)) * AKPAD
                               + (lane >> 4) * 8) * 2);
    uint32_t offK = (uint32_t)((((lane & 7) + (lane >> 4) * 8) * AKPAD
                               + ((lane >> 3) & 1) * 8) * 2);
    uint32_t offV = (uint32_t)((((lane & 7) + ((lane >> 3) & 1) * 8) * AKPAD
                               + (lane >> 4) * 8) * 2);

    float accO[8][4];
#pragma unroll
    for (int j = 0; j < 8; j++)
#pragma unroll
        for (int r = 0; r < 4; r++) accO[j][r] = 0.f;
    float m0 = -1e30f, m1 = -1e30f, l0 = 0.f, l1 = 0.f;

    uint32_t aQ[4][4];
    bool qLoaded = false;

    const int NT = SEQ / 64;
    for (int kt = 0; kt < NT; ++kt) {
        if (kt + 1 < NT) {
            loadKV((kt + 1) & 1, kt + 1);
            CP_COMMIT();
            CP_WAIT(1);
        } else {
            CP_WAIT(0);
        }
        __syncthreads();

        if (!qLoaded) {
#pragma unroll
            for (int k = 0; k < 4; k++) LDSM4(aQ[k], sb + offQ + k * 32);
            qLoaded = true;
        }

        uint32_t kbuf = sb + AQ_BYTES + (uint32_t)(2 * (kt & 1)) * AKV_BYTES;
        uint32_t vbuf = kbuf + AKV_BYTES;

        float accS[8][4];
#pragma unroll
        for (int j = 0; j < 8; j++)
#pragma unroll
            for (int r = 0; r < 4; r++) accS[j][r] = 0.f;
#pragma unroll
        for (int j2 = 0; j2 < 4; j2++) {
            uint32_t kb = kbuf + offK + (uint32_t)(j2 * 16 * AKPAD * 2);
#pragma unroll
            for (int kk = 0; kk < 4; kk++) {
                uint32_t b[4];
                LDSM4(b, kb + kk * 32);
                MMA16816(accS[j2 * 2],     aQ[kk], (b));
                MMA16816(accS[j2 * 2 + 1], aQ[kk], (b + 2));
            }
        }

        float mx0 = -1e30f, mx1 = -1e30f;
#pragma unroll
        for (int j = 0; j < 8; j++) {
            accS[j][0] *= SCALE; accS[j][1] *= SCALE;
            accS[j][2] *= SCALE; accS[j][3] *= SCALE;
            mx0 = fmaxf(mx0, fmaxf(accS[j][0], accS[j][1]));
            mx1 = fmaxf(mx1, fmaxf(accS[j][2], accS[j][3]));
        }
#pragma unroll
        for (int off = 1; off <= 2; off <<= 1) {
            mx0 = fmaxf(mx0, __shfl_xor_sync(0xffffffffu, mx0, off));
            mx1 = fmaxf(mx1, __shfl_xor_sync(0xffffffffu, mx1, off));
        }
        float nm0 = fmaxf(m0, mx0), nm1 = fmaxf(m1, mx1);
        float al0 = __expf(m0 - nm0), al1 = __expf(m1 - nm1);
        m0 = nm0; m1 = nm1;
        float ps0 = 0.f, ps1 = 0.f;
#pragma unroll
        for (int j = 0; j < 8; j++) {
            accS[j][0] = __expf(accS[j][0] - nm0);
            accS[j][1] = __expf(accS[j][1] - nm0);
            accS[j][2] = __expf(accS[j][2] - nm1);
            accS[j][3] = __expf(accS[j][3] - nm1);
            ps0 += accS[j][0] + accS[j][1];
            ps1 += accS[j][2] + accS[j][3];
        }
#pragma unroll
        for (int off = 1; off <= 2; off <<= 1) {
            ps0 += __shfl_xor_sync(0xffffffffu, ps0, off);
            ps1 += __shfl_xor_sync(0xffffffffu, ps1, off);
        }
        l0 = l0 * al0 + ps0;
        l1 = l1 * al1 + ps1;
#pragma unroll
        for (int j = 0; j < 8; j++) {
            accO[j][0] *= al0; accO[j][1] *= al0;
            accO[j][2] *= al1; accO[j][3] *= al1;
        }

        uint32_t aP[4][4];
#pragma unroll
        for (int kk = 0; kk < 4; kk++) {
            PACK_BF16X2(aP[kk][0], accS[2 * kk][0],     accS[2 * kk][1]);
            PACK_BF16X2(aP[kk][1], accS[2 * kk][2],     accS[2 * kk][3]);
            PACK_BF16X2(aP[kk][2], accS[2 * kk + 1][0], accS[2 * kk + 1][1]);
            PACK_BF16X2(aP[kk][3], accS[2 * kk + 1][2], accS[2 * kk + 1][3]);
        }

#pragma unroll
        for (int j2 = 0; j2 < 4; j2++) {
            uint32_t vb0 = vbuf + offV + (uint32_t)(j2 * 16 * 2);
#pragma unroll
            for (int kk = 0; kk < 4; kk++) {
                uint32_t b[4];
                LDSM4T(b, vb0 + (uint32_t)(kk * 16 * AKPAD * 2));
                MMA16816(accO[j2 * 2],     aP[kk], (b));
                MMA16816(accO[j2 * 2 + 1], aP[kk], (b + 2));
            }
        }
        __syncthreads();
    }

    float inv0 = 1.0f / l0, inv1 = 1.0f / l1;
    int r0 = q0 + wq0 + (lane >> 2);
    int cbase = hh * HD + (lane & 3) * 2;
#pragma unroll
    for (int j = 0; j < 8; j++) {
        int col = cbase + j * 8;
        uint32_t hi, lo;
        split2(accO[j][0] * inv0, accO[j][1] * inv0, hi, lo);
        size_t idx = (size_t)(bb * SEQ + r0) * DIM + col;
        *(uint32_t*)(oh + idx) = hi;
        *(uint32_t*)(ol + idx) = lo;
        split2(accO[j][2] * inv1, accO[j][3] * inv1, hi, lo);
        idx = (size_t)(bb * SEQ + r0 + 8) * DIM + col;
        *(uint32_t*)(oh + idx) = hi;
        *(uint32_t*)(ol + idx) = lo;
    }
}

// ---------------- driver -----------------------------------------------------
extern "C" void kernel_launch(void* const* d_in, const int* in_sizes, int n_in,
                              void* d_out, int out_size) {
    const float* x    = (const float*)d_in[0];
    const float* Wqkv = (const float*)d_in[1];
    const float* Wout = (const float*)d_in[2];
    const float* bout = (const float*)d_in[3];
    const float* ln1g = (const float*)d_in[4];
    const float* ln1b = (const float*)d_in[5];
    const float* ln2g = (const float*)d_in[6];
    const float* ln2b = (const float*)d_in[7];
    const float* W1   = (const float*)d_in[8];
    const float* b1   = (const float*)d_in[9];
    const float* W2   = (const float*)d_in[10];
    const float* b2   = (const float*)d_in[11];

    float* h = (float*)d_out;

    bf16 *pqkvb, *pyh, *pyl, *pah, *pal, *pmh, *pml;
    bf16 *pwqkvT, *pwoutT, *pw1T, *pw2T;
    cudaGetSymbolAddress((void**)&pqkvb,  g_qkvb);
    cudaGetSymbolAddress((void**)&pyh,    g_yh);
    cudaGetSymbolAddress((void**)&pyl,    g_yl);
    cudaGetSymbolAddress((void**)&pah,    g_ah);
    cudaGetSymbolAddress((void**)&pal,    g_al);
    cudaGetSymbolAddress((void**)&pmh,    g_mh);
    cudaGetSymbolAddress((void**)&pml,    g_ml);
    cudaGetSymbolAddress((void**)&pwqkvT, g_wqkvT);
    cudaGetSymbolAddress((void**)&pwoutT, g_woutT);
    cudaGetSymbolAddress((void**)&pw1T,   g_w1T);
    cudaGetSymbolAddress((void**)&pw2T,   g_w2T);

    cudaFuncSetAttribute(attn_mma_k, cudaFuncAttributeMaxDynamicSharedMemorySize, ATTM_SMEM);
    cudaFuncSetAttribute(gemm_mma_k<1>, cudaFuncAttributeMaxDynamicSharedMemorySize, GEMM_SMEM);
    cudaFuncSetAttribute(gemm_mma_k<2>, cudaFuncAttributeMaxDynamicSharedMemorySize, GEMM_SMEM);
    cudaFuncSetAttribute(gemm_mma_k<3>, cudaFuncAttributeMaxDynamicSharedMemorySize, GEMM_SMEM);

    const size_t SZ_QKV = (size_t)3 * DIM * DIM;
    const size_t SZ_OUT = (size_t)DIM * DIM;
    const size_t SZ_MLP = (size_t)DIM * MLPD;

    for (int l = 0; l < NLAYER; l++) {
        transpose_split_k<<<dim3(3 * DIM / 32, DIM / 32), 256>>>(
            Wqkv + (size_t)l * SZ_QKV,
            pwqkvT + (size_t)l * SZ_QKV, pwqkvT + ((size_t)NLAYER + l) * SZ_QKV,
            DIM, 3 * DIM);
        transpose_split_k<<<dim3(DIM / 32, DIM / 32), 256>>>(
            Wout + (size_t)l * SZ_OUT,
            pwoutT + (size_t)l * SZ_OUT, pwoutT + ((size_t)NLAYER + l) * SZ_OUT,
            DIM, DIM);
        transpose_split_k<<<dim3(MLPD / 32, DIM / 32), 256>>>(
            W1 + (size_t)l * SZ_MLP,
            pw1T + (size_t)l * SZ_MLP, pw1T + ((size_t)NLAYER + l) * SZ_MLP,
            DIM, MLPD);
        transpose_split_k<<<dim3(DIM / 32, MLPD / 32), 256>>>(
            W2 + (size_t)l * SZ_MLP,
            pw2T + (size_t)l * SZ_MLP, pw2T + ((size_t)NLAYER + l) * SZ_MLP,
            MLPD, DIM);
    }

    copy_kernel<<<TOK * DIM / (256 * 4), 256>>>(x, h);

    for (int l = 0; l < NLAYER; l++) {
        const float* bo  = bout + (size_t)l * DIM;
        const float* g1  = ln1g + (size_t)l * DIM;
        const float* bb1 = ln1b + (size_t)l * DIM;
        const float* g2  = ln2g + (size_t)l * DIM;
        const float* bb2 = ln2b + (size_t)l * DIM;
        const float* bf1 = b1 + (size_t)l * MLPD;
        const float* bf2 = b2 + (size_t)l * DIM;

        bf16* qkvT_h = pwqkvT + (size_t)l * SZ_QKV;
        bf16* qkvT_l = pwqkvT + ((size_t)NLAYER + l) * SZ_QKV;
        bf16* outT_h = pwoutT + (size_t)l * SZ_OUT;
        bf16* outT_l = pwoutT + ((size_t)NLAYER + l) * SZ_OUT;
        bf16* w1T_h  = pw1T + (size_t)l * SZ_MLP;
        bf16* w1T_l  = pw1T + ((size_t)NLAYER + l) * SZ_MLP;
        bf16* w2T_h  = pw2T + (size_t)l * SZ_MLP;
        bf16* w2T_l  = pw2T + ((size_t)NLAYER + l) * SZ_MLP;

        // --- attention block ---
        layernorm_k<<<TOK, 256>>>(h, g1, bb1, pyh, pyl);
        gemm_mma_k<3><<<dim3(3 * DIM / 256, TOK / 128), 256, GEMM_SMEM>>>(
            pyh, pyl, qkvT_h, qkvT_l, nullptr, nullptr, pqkvb, nullptr, 3 * DIM, DIM);
        attn_mma_k<<<dim3(SEQ / 128, HEADS, BATCH), 256, ATTM_SMEM>>>(pqkvb, pah, pal);
        gemm_mma_k<2><<<dim3(DIM / 256, TOK / 128), 256, GEMM_SMEM>>>(
            pah, pal, outT_h, outT_l, bo, h, nullptr, nullptr, DIM, DIM);

        // --- FFN block ---
        layernorm_k<<<TOK, 256>>>(h, g2, bb2, pyh, pyl);
        gemm_mma_k<1><<<dim3(MLPD / 256, TOK / 128), 256, GEMM_SMEM>>>(
            pyh, pyl, w1T_h, w1T_l, bf1, nullptr, pmh, pml, MLPD, DIM);
        gemm_mma_k<2><<<dim3(DIM / 256, TOK / 128), 256, GEMM_SMEM>>>(
            pmh, pml, w2T_h, w2T_l, bf2, h, nullptr, nullptr, DIM, MLPD);
    }
}

// round 8
// speedup vs baseline: 3.5351x; 1.2640x over previous
#include <cuda_runtime.h>
#include <cuda_fp16.h>
#include <math.h>
#include <stdint.h>

#define DIM    1024
#define SEQ    2048
#define BATCH  2
#define TOK    (BATCH*SEQ)   // 4096
#define HEADS  16
#define HD     64
#define MLPD   4096
#define NLAYER 6
#define SCALE  0.03125f
#define EPS    1e-5f

typedef __half f16;

// ---------------- scratch (static device globals; no allocation) ------------
__device__ f16  g_qkvh[TOK * 3 * DIM];                     // fp16 qkv for attention
__device__ f16  g_ya[TOK * DIM];                           // LN out (single fp16)
__device__ f16  g_att[TOK * DIM];                          // attention out
__device__ f16  g_mlp[(size_t)TOK * MLPD];                 // MLP hidden
// transposed+split weights [N,K] fp16, per layer, hi then lo
__device__ f16  g_wqkvT[2][NLAYER][3 * DIM * DIM];
__device__ f16  g_woutT[2][NLAYER][DIM * DIM];
__device__ f16  g_w1T[2][NLAYER][(size_t)DIM * MLPD];
__device__ f16  g_w2T[2][NLAYER][(size_t)DIM * MLPD];

// ---------------- PTX helpers (sm_80-class only: valid on plain sm_103) -----
__device__ __forceinline__ uint32_t smem_u32(const void* p) {
    uint32_t a;
    asm("{ .reg .u64 t; cvta.to.shared.u64 t, %1; cvt.u32.u64 %0, t; }"
        : "=r"(a) : "l"(p));
    return a;
}
#define LDSM4(r, addr) \
    asm volatile("ldmatrix.sync.aligned.m8n8.x4.shared.b16 {%0,%1,%2,%3}, [%4];" \
        : "=r"((r)[0]), "=r"((r)[1]), "=r"((r)[2]), "=r"((r)[3]) : "r"(addr))
#define LDSM4T(r, addr) \
    asm volatile("ldmatrix.sync.aligned.m8n8.x4.trans.shared.b16 {%0,%1,%2,%3}, [%4];" \
        : "=r"((r)[0]), "=r"((r)[1]), "=r"((r)[2]), "=r"((r)[3]) : "r"(addr))
#define MMA16816(d, a, b) \
    asm volatile("mma.sync.aligned.m16n8k16.row.col.f32.f16.f16.f32 " \
        "{%0,%1,%2,%3}, {%4,%5,%6,%7}, {%8,%9}, {%0,%1,%2,%3};" \
        : "+f"((d)[0]), "+f"((d)[1]), "+f"((d)[2]), "+f"((d)[3]) \
        : "r"((a)[0]), "r"((a)[1]), "r"((a)[2]), "r"((a)[3]), \
          "r"((b)[0]), "r"((b)[1]))
#define CP_ASYNC16(dst, src) \
    asm volatile("cp.async.cg.shared.global [%0], [%1], 16;" \
        :: "r"(dst), "l"(src) : "memory")
#define CP_COMMIT() asm volatile("cp.async.commit_group;" ::: "memory")
#define CP_WAIT(n)  asm volatile("cp.async.wait_group %0;" :: "n"(n) : "memory")
// packs {lo, hi} into one b32 (hi goes to upper half)
#define PACK_F16X2(d, lo, hi) \
    asm("cvt.rn.f16x2.f32 %0, %1, %2;" : "=r"(d) : "f"(hi), "f"(lo))

__device__ __forceinline__ float gelu_exact(float x) {
    return 0.5f * x * (1.0f + erff(x * 0.70710678118654752f));
}

// ---------------- simple copy ------------------------------------------------
__global__ __launch_bounds__(256) void copy_kernel(const float* __restrict__ in,
                                                   float* __restrict__ out) {
    size_t i = (size_t)blockIdx.x * 256 + threadIdx.x;
    ((float4*)out)[i] = ((const float4*)in)[i];
}

// ---------------- weight transpose + fp16 split: W[K,N] -> T{hi,lo}[N,K] ----
__global__ __launch_bounds__(256) void transpose_split_k(const float* __restrict__ W,
                                                         f16* __restrict__ Thi,
                                                         f16* __restrict__ Tlo,
                                                         int K, int N) {
    __shared__ float s[32][33];
    int n0 = blockIdx.x * 32, k0 = blockIdx.y * 32;
    int tx = threadIdx.x & 31, ty = threadIdx.x >> 5;   // ty 0..7
#pragma unroll
    for (int i = 0; i < 4; i++)
        s[ty + 8 * i][tx] = W[(size_t)(k0 + ty + 8 * i) * N + n0 + tx];
    __syncthreads();
#pragma unroll
    for (int i = 0; i < 4; i++) {
        float v = s[tx][ty + 8 * i];
        int n = n0 + ty + 8 * i, k = k0 + tx;
        f16 hi = __float2half(v);
        Thi[(size_t)n * K + k] = hi;
        Tlo[(size_t)n * K + k] = __float2half(v - __half2float(hi));
    }
}

// ---------------- layernorm -> single fp16 ------------------------------------
__global__ __launch_bounds__(256) void layernorm_k(const float* __restrict__ x,
                                                   const float* __restrict__ g,
                                                   const float* __restrict__ b,
                                                   f16* __restrict__ y) {
    int row = blockIdx.x;
    int t = threadIdx.x;
    float4 v = ((const float4*)(x + (size_t)row * DIM))[t];
    float s = v.x + v.y + v.z + v.w;
    float ss = v.x * v.x + v.y * v.y + v.z * v.z + v.w * v.w;
#pragma unroll
    for (int off = 16; off; off >>= 1) {
        s  += __shfl_xor_sync(0xffffffffu, s, off);
        ss += __shfl_xor_sync(0xffffffffu, ss, off);
    }
    __shared__ float sh[16];
    int w = t >> 5;
    if ((t & 31) == 0) { sh[w] = s; sh[8 + w] = ss; }
    __syncthreads();
    float S = 0.f, SS = 0.f;
#pragma unroll
    for (int i = 0; i < 8; i++) { S += sh[i]; SS += sh[8 + i]; }
    float mean = S * (1.0f / DIM);
    float var  = SS * (1.0f / DIM) - mean * mean;
    float r = rsqrtf(var + EPS);
    float4 gv = ((const float4*)g)[t];
    float4 bv = ((const float4*)b)[t];
    float o0 = (v.x - mean) * r * gv.x + bv.x;
    float o1 = (v.y - mean) * r * gv.y + bv.y;
    float o2 = (v.z - mean) * r * gv.z + bv.z;
    float o3 = (v.w - mean) * r * gv.w + bv.w;
    uint32_t p0, p1;
    PACK_F16X2(p0, o0, o1);
    PACK_F16X2(p1, o2, o3);
    *(uint2*)(y + (size_t)row * DIM + t * 4) = make_uint2(p0, p1);
}

// ---------------- warp-MMA split-fp16 GEMM -----------------------------------
// C[M,N] = A[M,K] @ B^T with B stored [N,K]; A single fp16, B (hi,lo) fp16.
// CTA tile 128x256, 8 warps (2 in m x 4 in n), warp tile 64x64, mma m16n8k16.
// EPI 1: gelu(AB + bias) -> O fp16
// EPI 2: C fp32 += AB + bias
// EPI 3: plain fp16 -> O
#define GBK    32                  // K-chunk
#define GSTR   40                  // smem row stride in f16 (80 B, conflict-free)
#define ATILE  (128 * GSTR * 2)    // 10240 B per A tile
#define BTILE  (256 * GSTR * 2)    // 20480 B per B tile
#define GSTAGE (ATILE + 2 * BTILE)       // A|Bhi|Blo = 51200 B
#define GEMM_SMEM (2 * GSTAGE)     // 102400 B

template <int EPI>
__global__ __launch_bounds__(256, 1) void gemm_mma_k(
    const f16* __restrict__ A,
    const f16* __restrict__ Bhi, const f16* __restrict__ Blo,
    const float* __restrict__ bias, float* __restrict__ C,
    f16* __restrict__ O,
    int N, int K) {
    extern __shared__ __align__(1024) char smem[];
    uint32_t sb = smem_u32(smem);
    int tid = threadIdx.x;
    int lane = tid & 31, wid = tid >> 5;
    int wm = wid & 1, wn = wid >> 1;          // warp grid 2 (m) x 4 (n)
    int bm = blockIdx.y * 128, bn = blockIdx.x * 256;

    // A ldmatrix lane offset (proven mapping)
    int matA = lane >> 3;                      // 0..3
    int rowA = wm * 64 + (matA & 1) * 8 + (lane & 7);
    int colA = (matA >> 1) * 8;
    uint32_t offA0 = (uint32_t)((rowA * GSTR + colA) * 2);
    // B ldmatrix lane offset (LDSM4 = two adjacent n8-tiles x two k8 halves)
    int rowB = wn * 64 + ((lane >> 4) & 1) * 8 + (lane & 7);
    int colB = ((lane >> 3) & 1) * 8;
    uint32_t offB0 = (uint32_t)((rowB * GSTR + colB) * 2) + (uint32_t)ATILE;

    float acc[4][8][4];
#pragma unroll
    for (int i = 0; i < 4; i++)
#pragma unroll
        for (int j = 0; j < 8; j++)
#pragma unroll
            for (int r = 0; r < 4; r++) acc[i][j][r] = 0.f;

    auto issue = [&](int s, int kc) {
        uint32_t stoff = sb + s * GSTAGE;
        // A tile: 512 transfers
#pragma unroll
        for (int it = 0; it < 2; ++it) {
            int idx = it * 256 + tid;
            int r = idx >> 2, c = idx & 3;
            CP_ASYNC16(stoff + (uint32_t)((r * GSTR + c * 8) * 2),
                       A + (size_t)(bm + r) * K + kc + c * 8);
        }
        // B tiles (hi, lo): 2 x 1024 transfers
#pragma unroll
        for (int it = 0; it < 8; ++it) {
            int idx = it * 256 + tid;
            int tl = idx >> 10;                // uniform per it
            int j = idx & 1023;
            int r = j >> 2, c = j & 3;
            const f16* src = tl ? Blo : Bhi;
            CP_ASYNC16(stoff + (uint32_t)ATILE + (uint32_t)tl * BTILE
                           + (uint32_t)((r * GSTR + c * 8) * 2),
                       src + (size_t)(bn + r) * K + kc + c * 8);
        }
    };

    issue(0, 0);
    CP_COMMIT();

    const int NC = K / GBK;
    for (int c = 0; c < NC; ++c) {
        if (c + 1 < NC) {
            issue((c + 1) & 1, (c + 1) * GBK);
            CP_COMMIT();
            CP_WAIT(1);
        } else {
            CP_WAIT(0);
        }
        __syncthreads();

        uint32_t st = sb + (c & 1) * GSTAGE;
#pragma unroll
        for (int kk = 0; kk < 2; ++kk) {
            uint32_t kb = st + kk * 32;
            uint32_t aF[4][4], bH[4][4], bL[4][4];
#pragma unroll
            for (int i = 0; i < 4; i++)
                LDSM4(aF[i], kb + offA0 + i * (16 * GSTR * 2));
#pragma unroll
            for (int j = 0; j < 4; j++) {
                LDSM4(bH[j], kb + offB0 + j * (16 * GSTR * 2));
                LDSM4(bL[j], kb + offB0 + j * (16 * GSTR * 2) + BTILE);
            }
#pragma unroll
            for (int i = 0; i < 4; i++)
#pragma unroll
                for (int j = 0; j < 4; j++) {
                    MMA16816(acc[i][2 * j],     aF[i], (bH[j]));
                    MMA16816(acc[i][2 * j + 1], aF[i], (bH[j] + 2));
                    MMA16816(acc[i][2 * j],     aF[i], (bL[j]));
                    MMA16816(acc[i][2 * j + 1], aF[i], (bL[j] + 2));
                }
        }
        __syncthreads();
    }

    int g = lane >> 2, tg = (lane & 3) * 2;
#pragma unroll
    for (int i = 0; i < 4; i++) {
        int row = bm + wm * 64 + i * 16 + g;
#pragma unroll
        for (int j = 0; j < 8; j++) {
            int col = bn + wn * 64 + j * 8 + tg;
#pragma unroll
            for (int half = 0; half < 2; half++) {
                int rr = row + half * 8;
                float v0 = acc[i][j][half * 2 + 0];
                float v1 = acc[i][j][half * 2 + 1];
                if (EPI == 1) {
                    float a0 = gelu_exact(v0 + __ldg(bias + col));
                    float a1 = gelu_exact(v1 + __ldg(bias + col + 1));
                    uint32_t p;
                    PACK_F16X2(p, a0, a1);
                    *(uint32_t*)(O + (size_t)rr * N + col) = p;
                } else if (EPI == 2) {
                    float2 old = *(float2*)(C + (size_t)rr * N + col);
                    old.x += v0 + __ldg(bias + col);
                    old.y += v1 + __ldg(bias + col + 1);
                    *(float2*)(C + (size_t)rr * N + col) = old;
                } else {
                    uint32_t p;
                    PACK_F16X2(p, v0, v1);
                    *(uint32_t*)(O + (size_t)rr * N + col) = p;
                }
            }
        }
    }
}

// ---------------- MMA flash attention (fp16 tensor, fp32 softmax) ------------
#define AKPAD  72                          // smem row stride (f16); 144B rows
#define AQ_BYTES (128 * AKPAD * 2)         // 18432
#define AKV_BYTES (64 * AKPAD * 2)         // 9216
#define ATTM_SMEM (AQ_BYTES + 4 * AKV_BYTES)   // 55296

__global__ __launch_bounds__(256, 1) void attn_mma_k(const f16* __restrict__ qkv,
                                                     f16* __restrict__ oa) {
    extern __shared__ __align__(1024) char smem[];
    uint32_t sb = smem_u32(smem);
    int tid = threadIdx.x;
    int lane = tid & 31, wid = tid >> 5;
    int q0 = blockIdx.x * 128;
    int hh = blockIdx.y;
    int bb = blockIdx.z;

    const size_t rstr = 3 * DIM;
    const f16* base = qkv + (size_t)(bb * SEQ) * rstr + hh * HD;

    {
#pragma unroll
        for (int it = 0; it < 4; ++it) {
            int idx = it * 256 + tid;
            int r = idx >> 3, c = idx & 7;
            CP_ASYNC16(sb + (uint32_t)(r * AKPAD + c * 8) * 2,
                       base + (size_t)(q0 + r) * rstr + c * 8);
        }
    }
    auto loadKV = [&](int s, int kt) {
        uint32_t kbuf = sb + AQ_BYTES + (uint32_t)(2 * s) * AKV_BYTES;
        uint32_t vbuf = kbuf + AKV_BYTES;
#pragma unroll
        for (int it = 0; it < 2; ++it) {
            int idx = it * 256 + tid;
            int r = idx >> 3, c = idx & 7;
            const f16* kp = base + DIM + (size_t)(kt * 64 + r) * rstr + c * 8;
            const f16* vp = base + 2 * DIM + (size_t)(kt * 64 + r) * rstr + c * 8;
            uint32_t off = (uint32_t)(r * AKPAD + c * 8) * 2;
            CP_ASYNC16(kbuf + off, kp);
            CP_ASYNC16(vbuf + off, vp);
        }
    };

    loadKV(0, 0);
    CP_COMMIT();

    int wq0 = wid * 16;
    uint32_t offQ = (uint32_t)(((wq0 + ((lane >> 3) & 1) * 8 + (lane & 7)) * AKPAD
                               + (lane >> 4) * 8) * 2);
    uint32_t offK = (uint32_t)((((lane & 7) + (lane >> 4) * 8) * AKPAD
                               + ((lane >> 3) & 1) * 8) * 2);
    uint32_t offV = (uint32_t)((((lane & 7) + ((lane >> 3) & 1) * 8) * AKPAD
                               + (lane >> 4) * 8) * 2);

    float accO[8][4];
#pragma unroll
    for (int j = 0; j < 8; j++)
#pragma unroll
        for (int r = 0; r < 4; r++) accO[j][r] = 0.f;
    float m0 = -1e30f, m1 = -1e30f, l0 = 0.f, l1 = 0.f;

    uint32_t aQ[4][4];
    bool qLoaded = false;

    const int NT = SEQ / 64;
    for (int kt = 0; kt < NT; ++kt) {
        if (kt + 1 < NT) {
            loadKV((kt + 1) & 1, kt + 1);
            CP_COMMIT();
            CP_WAIT(1);
        } else {
            CP_WAIT(0);
        }
        __syncthreads();

        if (!qLoaded) {
#pragma unroll
            for (int k = 0; k < 4; k++) LDSM4(aQ[k], sb + offQ + k * 32);
            qLoaded = true;
        }

        uint32_t kbuf = sb + AQ_BYTES + (uint32_t)(2 * (kt & 1)) * AKV_BYTES;
        uint32_t vbuf = kbuf + AKV_BYTES;

        float accS[8][4];
#pragma unroll
        for (int j = 0; j < 8; j++)
#pragma unroll
            for (int r = 0; r < 4; r++) accS[j][r] = 0.f;
#pragma unroll
        for (int j2 = 0; j2 < 4; j2++) {
            uint32_t kb = kbuf + offK + (uint32_t)(j2 * 16 * AKPAD * 2);
#pragma unroll
            for (int kk = 0; kk < 4; kk++) {
                uint32_t b[4];
                LDSM4(b, kb + kk * 32);
                MMA16816(accS[j2 * 2],     aQ[kk], (b));
                MMA16816(accS[j2 * 2 + 1], aQ[kk], (b + 2));
            }
        }

        float mx0 = -1e30f, mx1 = -1e30f;
#pragma unroll
        for (int j = 0; j < 8; j++) {
            accS[j][0] *= SCALE; accS[j][1] *= SCALE;
            accS[j][2] *= SCALE; accS[j][3] *= SCALE;
            mx0 = fmaxf(mx0, fmaxf(accS[j][0], accS[j][1]));
            mx1 = fmaxf(mx1, fmaxf(accS[j][2], accS[j][3]));
        }
#pragma unroll
        for (int off = 1; off <= 2; off <<= 1) {
            mx0 = fmaxf(mx0, __shfl_xor_sync(0xffffffffu, mx0, off));
            mx1 = fmaxf(mx1, __shfl_xor_sync(0xffffffffu, mx1, off));
        }
        float nm0 = fmaxf(m0, mx0), nm1 = fmaxf(m1, mx1);
        float al0 = __expf(m0 - nm0), al1 = __expf(m1 - nm1);
        m0 = nm0; m1 = nm1;
        float ps0 = 0.f, ps1 = 0.f;
#pragma unroll
        for (int j = 0; j < 8; j++) {
            accS[j][0] = __expf(accS[j][0] - nm0);
            accS[j][1] = __expf(accS[j][1] - nm0);
            accS[j][2] = __expf(accS[j][2] - nm1);
            accS[j][3] = __expf(accS[j][3] - nm1);
            ps0 += accS[j][0] + accS[j][1];
            ps1 += accS[j][2] + accS[j][3];
        }
#pragma unroll
        for (int off = 1; off <= 2; off <<= 1) {
            ps0 += __shfl_xor_sync(0xffffffffu, ps0, off);
            ps1 += __shfl_xor_sync(0xffffffffu, ps1, off);
        }
        l0 = l0 * al0 + ps0;
        l1 = l1 * al1 + ps1;
#pragma unroll
        for (int j = 0; j < 8; j++) {
            accO[j][0] *= al0; accO[j][1] *= al0;
            accO[j][2] *= al1; accO[j][3] *= al1;
        }

        uint32_t aP[4][4];
#pragma unroll
        for (int kk = 0; kk < 4; kk++) {
            PACK_F16X2(aP[kk][0], accS[2 * kk][0],     accS[2 * kk][1]);
            PACK_F16X2(aP[kk][1], accS[2 * kk][2],     accS[2 * kk][3]);
            PACK_F16X2(aP[kk][2], accS[2 * kk + 1][0], accS[2 * kk + 1][1]);
            PACK_F16X2(aP[kk][3], accS[2 * kk + 1][2], accS[2 * kk + 1][3]);
        }

#pragma unroll
        for (int j2 = 0; j2 < 4; j2++) {
            uint32_t vb0 = vbuf + offV + (uint32_t)(j2 * 16 * 2);
#pragma unroll
            for (int kk = 0; kk < 4; kk++) {
                uint32_t b[4];
                LDSM4T(b, vb0 + (uint32_t)(kk * 16 * AKPAD * 2));
                MMA16816(accO[j2 * 2],     aP[kk], (b));
                MMA16816(accO[j2 * 2 + 1], aP[kk], (b + 2));
            }
        }
        __syncthreads();
    }

    float inv0 = 1.0f / l0, inv1 = 1.0f / l1;
    int r0 = q0 + wq0 + (lane >> 2);
    int cbase = hh * HD + (lane & 3) * 2;
#pragma unroll
    for (int j = 0; j < 8; j++) {
        int col = cbase + j * 8;
        uint32_t p;
        PACK_F16X2(p, accO[j][0] * inv0, accO[j][1] * inv0);
        size_t idx = (size_t)(bb * SEQ + r0) * DIM + col;
        *(uint32_t*)(oa + idx) = p;
        PACK_F16X2(p, accO[j][2] * inv1, accO[j][3] * inv1);
        idx = (size_t)(bb * SEQ + r0 + 8) * DIM + col;
        *(uint32_t*)(oa + idx) = p;
    }
}

// ---------------- driver -----------------------------------------------------
extern "C" void kernel_launch(void* const* d_in, const int* in_sizes, int n_in,
                              void* d_out, int out_size) {
    const float* x    = (const float*)d_in[0];
    const float* Wqkv = (const float*)d_in[1];
    const float* Wout = (const float*)d_in[2];
    const float* bout = (const float*)d_in[3];
    const float* ln1g = (const float*)d_in[4];
    const float* ln1b = (const float*)d_in[5];
    const float* ln2g = (const float*)d_in[6];
    const float* ln2b = (const float*)d_in[7];
    const float* W1   = (const float*)d_in[8];
    const float* b1   = (const float*)d_in[9];
    const float* W2   = (const float*)d_in[10];
    const float* b2   = (const float*)d_in[11];

    float* h = (float*)d_out;

    f16 *pqkvh, *pya, *patt, *pmlp;
    f16 *pwqkvT, *pwoutT, *pw1T, *pw2T;
    cudaGetSymbolAddress((void**)&pqkvh,  g_qkvh);
    cudaGetSymbolAddress((void**)&pya,    g_ya);
    cudaGetSymbolAddress((void**)&patt,   g_att);
    cudaGetSymbolAddress((void**)&pmlp,   g_mlp);
    cudaGetSymbolAddress((void**)&pwqkvT, g_wqkvT);
    cudaGetSymbolAddress((void**)&pwoutT, g_woutT);
    cudaGetSymbolAddress((void**)&pw1T,   g_w1T);
    cudaGetSymbolAddress((void**)&pw2T,   g_w2T);

    cudaFuncSetAttribute(attn_mma_k, cudaFuncAttributeMaxDynamicSharedMemorySize, ATTM_SMEM);
    cudaFuncSetAttribute(gemm_mma_k<1>, cudaFuncAttributeMaxDynamicSharedMemorySize, GEMM_SMEM);
    cudaFuncSetAttribute(gemm_mma_k<2>, cudaFuncAttributeMaxDynamicSharedMemorySize, GEMM_SMEM);
    cudaFuncSetAttribute(gemm_mma_k<3>, cudaFuncAttributeMaxDynamicSharedMemorySize, GEMM_SMEM);

    const size_t SZ_QKV = (size_t)3 * DIM * DIM;
    const size_t SZ_OUT = (size_t)DIM * DIM;
    const size_t SZ_MLP = (size_t)DIM * MLPD;

    for (int l = 0; l < NLAYER; l++) {
        transpose_split_k<<<dim3(3 * DIM / 32, DIM / 32), 256>>>(
            Wqkv + (size_t)l * SZ_QKV,
            pwqkvT + (size_t)l * SZ_QKV, pwqkvT + ((size_t)NLAYER + l) * SZ_QKV,
            DIM, 3 * DIM);
        transpose_split_k<<<dim3(DIM / 32, DIM / 32), 256>>>(
            Wout + (size_t)l * SZ_OUT,
            pwoutT + (size_t)l * SZ_OUT, pwoutT + ((size_t)NLAYER + l) * SZ_OUT,
            DIM, DIM);
        transpose_split_k<<<dim3(MLPD / 32, DIM / 32), 256>>>(
            W1 + (size_t)l * SZ_MLP,
            pw1T + (size_t)l * SZ_MLP, pw1T + ((size_t)NLAYER + l) * SZ_MLP,
            DIM, MLPD);
        transpose_split_k<<<dim3(DIM / 32, MLPD / 32), 256>>>(
            W2 + (size_t)l * SZ_MLP,
            pw2T + (size_t)l * SZ_MLP, pw2T + ((size_t)NLAYER + l) * SZ_MLP,
            MLPD, DIM);
    }

    copy_kernel<<<TOK * DIM / (256 * 4), 256>>>(x, h);

    for (int l = 0; l < NLAYER; l++) {
        const float* bo  = bout + (size_t)l * DIM;
        const float* g1  = ln1g + (size_t)l * DIM;
        const float* bb1 = ln1b + (size_t)l * DIM;
        const float* g2  = ln2g + (size_t)l * DIM;
        const float* bb2 = ln2b + (size_t)l * DIM;
        const float* bf1 = b1 + (size_t)l * MLPD;
        const float* bf2 = b2 + (size_t)l * DIM;

        f16* qkvT_h = pwqkvT + (size_t)l * SZ_QKV;
        f16* qkvT_l = pwqkvT + ((size_t)NLAYER + l) * SZ_QKV;
        f16* outT_h = pwoutT + (size_t)l * SZ_OUT;
        f16* outT_l = pwoutT + ((size_t)NLAYER + l) * SZ_OUT;
        f16* w1T_h  = pw1T + (size_t)l * SZ_MLP;
        f16* w1T_l  = pw1T + ((size_t)NLAYER + l) * SZ_MLP;
        f16* w2T_h  = pw2T + (size_t)l * SZ_MLP;
        f16* w2T_l  = pw2T + ((size_t)NLAYER + l) * SZ_MLP;

        // --- attention block ---
        layernorm_k<<<TOK, 256>>>(h, g1, bb1, pya);
        gemm_mma_k<3><<<dim3(3 * DIM / 256, TOK / 128), 256, GEMM_SMEM>>>(
            pya, qkvT_h, qkvT_l, nullptr, nullptr, pqkvh, 3 * DIM, DIM);
        attn_mma_k<<<dim3(SEQ / 128, HEADS, BATCH), 256, ATTM_SMEM>>>(pqkvh, patt);
        gemm_mma_k<2><<<dim3(DIM / 256, TOK / 128), 256, GEMM_SMEM>>>(
            patt, outT_h, outT_l, bo, h, nullptr, DIM, DIM);

        // --- FFN block ---
        layernorm_k<<<TOK, 256>>>(h, g2, bb2, pya);
        gemm_mma_k<1><<<dim3(MLPD / 256, TOK / 128), 256, GEMM_SMEM>>>(
            pya, w1T_h, w1T_l, bf1, nullptr, pmlp, MLPD, DIM);
        gemm_mma_k<2><<<dim3(DIM / 256, TOK / 128), 256, GEMM_SMEM>>>(
            pmlp, w2T_h, w2T_l, bf2, h, nullptr, DIM, MLPD);
    }
}